// round 9
// baseline (speedup 1.0000x reference)
#include <cuda_runtime.h>
#include <cuda_bf16.h>
#include <cstdint>

// Shapes (fixed): B=2, S=2048, D=1024, H=16, d=64
// head h of batch b = contiguous block (b*2048 + h*128)*1024 viewed as [2048,64] row-major
// d_out = [ proj : 4194304 f32 ][ attn : 134217728 f32 ]

#define PROJ_ELEMS 4194304LL
#define HEAD_STRIDE 131072LL
#define ATTN_STRIDE 4194304LL

// ---------------- persistent bf16 split buffers (device globals) ----------------
__device__ __nv_bfloat16 g_preh[12582912], g_prel[12582912];   // pre_q|pre_k|pre_v
__device__ __nv_bfloat16 g_Wh[3145728],   g_Wl[3145728];       // Wq|Wk|Wv
__device__ __nv_bfloat16 g_Woh[1048576],  g_Wol[1048576];
__device__ float         g_bias3[3072];                        // bq|bk|bv
__device__ __nv_bfloat16 g_QKVh[12582912], g_QKVl[12582912];   // Q|K|V (hi/lo)
__device__ __nv_bfloat16 g_Vth[4194304],  g_Vtl[4194304];      // V transposed [head][64][2048]
__device__ __nv_bfloat16 g_Oh[4194304],   g_Ol[4194304];

// ---------------- helpers ----------------
__device__ __forceinline__ uint32_t smem_u32(const void* p) {
    return (uint32_t)__cvta_generic_to_shared(p);
}
__device__ __forceinline__ void cpa16(__nv_bfloat16* s, const __nv_bfloat16* g) {
    asm volatile("cp.async.cg.shared.global [%0], [%1], 16;"
                 :: "r"(smem_u32(s)), "l"(__cvta_generic_to_global(g)));
}
__device__ __forceinline__ void cp_commit() { asm volatile("cp.async.commit_group;"); }
template<int NW> __device__ __forceinline__ void cp_wait() {
    asm volatile("cp.async.wait_group %0;" :: "n"(NW));
}
__device__ __forceinline__ void ldmx4(uint32_t& r0, uint32_t& r1, uint32_t& r2, uint32_t& r3,
                                      uint32_t addr) {
    asm volatile("ldmatrix.sync.aligned.m8n8.x4.shared.b16 {%0,%1,%2,%3}, [%4];"
                 : "=r"(r0), "=r"(r1), "=r"(r2), "=r"(r3) : "r"(addr));
}
__device__ __forceinline__ void mma16(float* c, const uint32_t* a, const uint32_t* b) {
    asm volatile(
        "mma.sync.aligned.m16n8k16.row.col.f32.bf16.bf16.f32 "
        "{%0,%1,%2,%3},{%4,%5,%6,%7},{%8,%9},{%0,%1,%2,%3};"
        : "+f"(c[0]), "+f"(c[1]), "+f"(c[2]), "+f"(c[3])
        : "r"(a[0]), "r"(a[1]), "r"(a[2]), "r"(a[3]), "r"(b[0]), "r"(b[1]));
}
__device__ __forceinline__ void store_split2(__nv_bfloat16* h, __nv_bfloat16* l,
                                             float a, float b) {
    __nv_bfloat16 ha = __float2bfloat16(a), hb = __float2bfloat16(b);
    __nv_bfloat16 la = __float2bfloat16(a - __bfloat162float(ha));
    __nv_bfloat16 lb = __float2bfloat16(b - __bfloat162float(hb));
    __nv_bfloat162 hp; hp.x = ha; hp.y = hb;
    __nv_bfloat162 lp; lp.x = la; lp.y = lb;
    *(__nv_bfloat162*)h = hp;
    *(__nv_bfloat162*)l = lp;
}

#define SPAD 40   // smem row stride for gemm3 tiles

// ---------------------------------------------------------------------------
// prep kernels
// ---------------------------------------------------------------------------
__global__ void splitk(const float4* __restrict__ x,
                       __nv_bfloat16* __restrict__ h, __nv_bfloat16* __restrict__ l, int n4)
{
    int i = blockIdx.x * blockDim.x + threadIdx.x;
    if (i >= n4) return;
    float4 v = x[i];
    float vs[4] = {v.x, v.y, v.z, v.w};
    __nv_bfloat16 hh[4], ll[4];
    #pragma unroll
    for (int c = 0; c < 4; c++) {
        hh[c] = __float2bfloat16(vs[c]);
        ll[c] = __float2bfloat16(vs[c] - __bfloat162float(hh[c]));
    }
    __nv_bfloat162 h0; h0.x = hh[0]; h0.y = hh[1];
    __nv_bfloat162 h1; h1.x = hh[2]; h1.y = hh[3];
    __nv_bfloat162 l0; l0.x = ll[0]; l0.y = ll[1];
    __nv_bfloat162 l1; l1.x = ll[2]; l1.y = ll[3];
    *(__nv_bfloat162*)(h + 4 * i)     = h0;
    *(__nv_bfloat162*)(h + 4 * i + 2) = h1;
    *(__nv_bfloat162*)(l + 4 * i)     = l0;
    *(__nv_bfloat162*)(l + 4 * i + 2) = l1;
}

__global__ void biascopy(const float* __restrict__ bq, const float* __restrict__ bk,
                         const float* __restrict__ bv, float* __restrict__ dst)
{
    int i = blockIdx.x * blockDim.x + threadIdx.x;
    if (i < 1024) { dst[i] = bq[i]; dst[1024 + i] = bk[i]; dst[2048 + i] = bv[i]; }
}

// Transpose V per head: [2048,64] -> [64,2048], hi and lo.
__global__ __launch_bounds__(256) void transposeV(
    const __nv_bfloat16* __restrict__ Vh, const __nv_bfloat16* __restrict__ Vl,
    __nv_bfloat16* __restrict__ Vth, __nv_bfloat16* __restrict__ Vtl)
{
    __shared__ __nv_bfloat16 th[64][72], tl[64][72];
    const long head = blockIdx.y;
    const int  k0   = blockIdx.x * 64;
    const __nv_bfloat16* inh = Vh + head * HEAD_STRIDE + (long)k0 * 64;
    const __nv_bfloat16* inl = Vl + head * HEAD_STRIDE + (long)k0 * 64;
    __nv_bfloat16* outh = Vth + head * HEAD_STRIDE + k0;
    __nv_bfloat16* outl = Vtl + head * HEAD_STRIDE + k0;

    const int tid = threadIdx.x;
    const int lr = tid >> 2, seg = tid & 3;
    #pragma unroll
    for (int i = 0; i < 2; i++) {
        int col = seg * 16 + i * 8;
        *(uint4*)&th[lr][col] = *(const uint4*)(inh + (long)lr * 64 + col);
        *(uint4*)&tl[lr][col] = *(const uint4*)(inl + (long)lr * 64 + col);
    }
    __syncthreads();
    #pragma unroll
    for (int i = 0; i < 2; i++) {
        int kk = seg * 16 + i * 8;
        __nv_bfloat16 eh[8], el[8];
        #pragma unroll
        for (int j = 0; j < 8; j++) { eh[j] = th[kk + j][lr]; el[j] = tl[kk + j][lr]; }
        *(uint4*)(outh + (long)lr * 2048 + kk) = *(uint4*)eh;
        *(uint4*)(outl + (long)lr * 2048 + kk) = *(uint4*)el;
    }
}

// ---------------------------------------------------------------------------
// gemm3: 3-pass split-bf16 NT GEMM, cp.async 2-stage pipelined (unchanged R8).
// ---------------------------------------------------------------------------
template<int EPI>
__global__ __launch_bounds__(256) void gemm3(
    const __nv_bfloat16* __restrict__ Ah, const __nv_bfloat16* __restrict__ Al,
    const __nv_bfloat16* __restrict__ Bh, const __nv_bfloat16* __restrict__ Bl,
    const float* __restrict__ bias, float* __restrict__ C,
    __nv_bfloat16* __restrict__ Ch, __nv_bfloat16* __restrict__ Cl,
    int M, int N, int K, float alpha,
    long zsA, long zsB, long zsC, int zsBias)
{
    extern __shared__ __align__(16) __nv_bfloat16 sm[];
    const long z = blockIdx.z;
    Ah += z * zsA; Al += z * zsA;
    Bh += z * zsB; Bl += z * zsB;
    const float* bz = bias ? bias + (long)z * zsBias : nullptr;

    const int tid = threadIdx.x, warp = tid >> 5, lane = tid & 31;
    const int g = lane >> 2, t = lane & 3, wm = warp >> 2, wn = warp & 3;
    const int lrow = lane & 15, lkof = (lane & 16) >> 1;
    const int rowC = blockIdx.y * 128, colC = blockIdx.x * 128;

    const __nv_bfloat16* srcs[4] = { Ah + (long)rowC * K, Al + (long)rowC * K,
                                     Bh + (long)colC * K, Bl + (long)colC * K };

    float acc[4][4][4];
    #pragma unroll
    for (int mi = 0; mi < 4; mi++)
        #pragma unroll
        for (int ni = 0; ni < 4; ni++)
            #pragma unroll
            for (int r = 0; r < 4; r++) acc[mi][ni][r] = 0.f;

    const int rr0 = tid >> 2,            ss0 = tid & 3;
    const int rr1 = (tid + 256) >> 2,    ss1 = (tid + 256) & 3;

    auto load_stage = [&](int stg, int k0) {
        __nv_bfloat16* base = sm + stg * 4 * (128 * SPAD);
        #pragma unroll
        for (int m = 0; m < 4; m++) {
            __nv_bfloat16* d = base + m * (128 * SPAD);
            cpa16(d + rr0 * SPAD + ss0 * 8, srcs[m] + (long)rr0 * K + k0 + ss0 * 8);
            cpa16(d + rr1 * SPAD + ss1 * 8, srcs[m] + (long)rr1 * K + k0 + ss1 * 8);
        }
    };

    auto compute = [&](int stg) {
        const __nv_bfloat16* bAh = sm + (stg * 4 + 0) * (128 * SPAD);
        const __nv_bfloat16* bAl = sm + (stg * 4 + 1) * (128 * SPAD);
        const __nv_bfloat16* bBh = sm + (stg * 4 + 2) * (128 * SPAD);
        const __nv_bfloat16* bBl = sm + (stg * 4 + 3) * (128 * SPAD);
        #pragma unroll
        for (int ks = 0; ks < 2; ks++) {
            const int kb = ks * 16 + lkof;
            uint32_t bh[4][2], bl[4][2];
            #pragma unroll
            for (int p = 0; p < 2; p++) {
                int n = wn * 32 + p * 16 + lrow;
                uint32_t r0, r1, r2, r3;
                ldmx4(r0, r1, r2, r3, smem_u32(bBh + n * SPAD + kb));
                bh[2*p][0] = r0; bh[2*p+1][0] = r1; bh[2*p][1] = r2; bh[2*p+1][1] = r3;
                ldmx4(r0, r1, r2, r3, smem_u32(bBl + n * SPAD + kb));
                bl[2*p][0] = r0; bl[2*p+1][0] = r1; bl[2*p][1] = r2; bl[2*p+1][1] = r3;
            }
            #pragma unroll
            for (int mi = 0; mi < 4; mi++) {
                int mrow = wm * 64 + mi * 16 + lrow;
                uint32_t ah[4], al[4];
                ldmx4(ah[0], ah[1], ah[2], ah[3], smem_u32(bAh + mrow * SPAD + kb));
                ldmx4(al[0], al[1], al[2], al[3], smem_u32(bAl + mrow * SPAD + kb));
                #pragma unroll
                for (int ni = 0; ni < 4; ni++) {
                    mma16(acc[mi][ni], ah, bh[ni]);
                    mma16(acc[mi][ni], ah, bl[ni]);
                    mma16(acc[mi][ni], al, bh[ni]);
                }
            }
        }
    };

    const int KT = K >> 5;
    load_stage(0, 0); cp_commit();
    for (int kt = 0; kt < KT; kt++) {
        if (kt + 1 < KT) { load_stage((kt + 1) & 1, (kt + 1) * 32); cp_commit(); cp_wait<1>(); }
        else             { cp_wait<0>(); }
        __syncthreads();
        compute(kt & 1);
        __syncthreads();
    }

    float*         Cz  = (EPI == 0) ? C  + z * zsC : nullptr;
    __nv_bfloat16* Chz = (EPI == 1) ? Ch + z * zsC : nullptr;
    __nv_bfloat16* Clz = (EPI == 1) ? Cl + z * zsC : nullptr;

    #pragma unroll
    for (int mi = 0; mi < 4; mi++) {
        #pragma unroll
        for (int ni = 0; ni < 4; ni++) {
            int r0 = rowC + wm * 64 + mi * 16 + g;
            int cc = colC + wn * 32 + ni * 8 + 2 * t;
            float b0 = bz ? bz[cc] : 0.f, b1 = bz ? bz[cc + 1] : 0.f;
            float c00 = fmaf(acc[mi][ni][0], alpha, b0);
            float c01 = fmaf(acc[mi][ni][1], alpha, b1);
            float c10 = fmaf(acc[mi][ni][2], alpha, b0);
            float c11 = fmaf(acc[mi][ni][3], alpha, b1);
            if (EPI == 0) {
                float2 o0 = {c00, c01}, o1 = {c10, c11};
                *(float2*)(Cz + (long)r0 * N + cc)       = o0;
                *(float2*)(Cz + (long)(r0 + 8) * N + cc) = o1;
            } else {
                store_split2(Chz + (long)r0 * N + cc,       Clz + (long)r0 * N + cc,       c00, c01);
                store_split2(Chz + (long)(r0 + 8) * N + cc, Clz + (long)(r0 + 8) * N + cc, c10, c11);
            }
        }
    }
}

// ---------------------------------------------------------------------------
// fused_attn: per (head z, 128-row strip rb):
//   Pass 1: stream K tiles, S = Q K^T / 8 (3-pass split-bf16 MMA), online row max/expsum.
//   Pass 2: re-stream K + V tiles, recompute S, p = exp(s-m)*inv,
//           write p (fp32) to attn, split p -> smem, O += P @ V (3-pass).
// 256 threads, 8 warps (2x4). Smem carve (bytes):
//   Qh/Ql 2*18432 | K 2buf*2*9216*2 | Vh/Vl 2*17408 | Ph/Pl 2*34816 | red 4096 | fm/fi 1024
// total 220160.
// ---------------------------------------------------------------------------
#define QSTR 72
#define VSTR 136

__global__ __launch_bounds__(256, 1) void fused_attn(
    const __nv_bfloat16* __restrict__ QKVh, const __nv_bfloat16* __restrict__ QKVl,
    const __nv_bfloat16* __restrict__ Vth,  const __nv_bfloat16* __restrict__ Vtl,
    float* __restrict__ attn,
    __nv_bfloat16* __restrict__ Oh, __nv_bfloat16* __restrict__ Ol)
{
    extern __shared__ __align__(16) char smraw[];
    __nv_bfloat16* sb  = (__nv_bfloat16*)smraw;
    __nv_bfloat16* sQh = sb;                 // 128*72 = 9216
    __nv_bfloat16* sQl = sb + 9216;
    // K buffers at sb + 18432 + b*18432 (Kh), +9216 (Kl)
    __nv_bfloat16* sVh = sb + 55296;         // 64*136 = 8704
    __nv_bfloat16* sVl = sb + 64000;
    __nv_bfloat16* sPh = sb + 72704;         // 128*136 = 17408
    __nv_bfloat16* sPl = sb + 90112;
    float* redm = (float*)(smraw + 215040);  // [4][128]
    float* reds = (float*)(smraw + 217088);
    float* fm   = (float*)(smraw + 219136);  // [128]
    float* fi   = (float*)(smraw + 219648);

    const int tid = threadIdx.x, warp = tid >> 5, lane = tid & 31;
    const int g = lane >> 2, t = lane & 3, wm = warp >> 2, wn = warp & 3;
    const int lrow = lane & 15, lkof = (lane & 16) >> 1;

    const long z  = blockIdx.y;
    const int  rb = blockIdx.x;
    const __nv_bfloat16* Qh_g = QKVh + z * HEAD_STRIDE + (long)rb * 128 * 64;
    const __nv_bfloat16* Ql_g = QKVl + z * HEAD_STRIDE + (long)rb * 128 * 64;
    const __nv_bfloat16* Kh_g = QKVh + 4194304 + z * HEAD_STRIDE;
    const __nv_bfloat16* Kl_g = QKVl + 4194304 + z * HEAD_STRIDE;
    const __nv_bfloat16* Vh_g = Vth + z * HEAD_STRIDE;
    const __nv_bfloat16* Vl_g = Vtl + z * HEAD_STRIDE;
    float* attnZ = attn + z * ATTN_STRIDE + (long)rb * 128 * 2048;

    auto loadQ = [&]() {
        #pragma unroll
        for (int i = 0; i < 4; i++) {
            int idx = tid + i * 256, r = idx >> 3, c = idx & 7;
            cpa16(sQh + r * QSTR + c * 8, Qh_g + r * 64 + c * 8);
            cpa16(sQl + r * QSTR + c * 8, Ql_g + r * 64 + c * 8);
        }
    };
    auto loadK = [&](int kt, int b) {
        __nv_bfloat16* dh = sb + 18432 + b * 18432;
        __nv_bfloat16* dl = dh + 9216;
        const __nv_bfloat16* gh = Kh_g + (long)kt * 128 * 64;
        const __nv_bfloat16* gl = Kl_g + (long)kt * 128 * 64;
        #pragma unroll
        for (int i = 0; i < 4; i++) {
            int idx = tid + i * 256, r = idx >> 3, c = idx & 7;
            cpa16(dh + r * QSTR + c * 8, gh + r * 64 + c * 8);
            cpa16(dl + r * QSTR + c * 8, gl + r * 64 + c * 8);
        }
    };
    auto loadV = [&](int kt) {
        #pragma unroll
        for (int i = 0; i < 4; i++) {
            int idx = tid + i * 256, r = idx >> 4, c = idx & 15;
            cpa16(sVh + r * VSTR + c * 8, Vh_g + (long)r * 2048 + kt * 128 + c * 8);
            cpa16(sVl + r * VSTR + c * 8, Vl_g + (long)r * 2048 + kt * 128 + c * 8);
        }
    };

    float accS[4][4][4];
    auto computeS = [&](int b) {
        const __nv_bfloat16* bKh = sb + 18432 + b * 18432;
        const __nv_bfloat16* bKl = bKh + 9216;
        #pragma unroll
        for (int mi = 0; mi < 4; mi++)
            #pragma unroll
            for (int ni = 0; ni < 4; ni++)
                #pragma unroll
                for (int r = 0; r < 4; r++) accS[mi][ni][r] = 0.f;
        #pragma unroll
        for (int ks = 0; ks < 4; ks++) {
            int kb = ks * 16 + lkof;
            uint32_t bh[4][2], bl[4][2];
            #pragma unroll
            for (int p = 0; p < 2; p++) {
                int n = wn * 32 + p * 16 + lrow;
                uint32_t r0, r1, r2, r3;
                ldmx4(r0, r1, r2, r3, smem_u32(bKh + n * QSTR + kb));
                bh[2*p][0] = r0; bh[2*p+1][0] = r1; bh[2*p][1] = r2; bh[2*p+1][1] = r3;
                ldmx4(r0, r1, r2, r3, smem_u32(bKl + n * QSTR + kb));
                bl[2*p][0] = r0; bl[2*p+1][0] = r1; bl[2*p][1] = r2; bl[2*p+1][1] = r3;
            }
            #pragma unroll
            for (int mi = 0; mi < 4; mi++) {
                int m = wm * 64 + mi * 16 + lrow;
                uint32_t ah[4], al[4];
                ldmx4(ah[0], ah[1], ah[2], ah[3], smem_u32(sQh + m * QSTR + kb));
                ldmx4(al[0], al[1], al[2], al[3], smem_u32(sQl + m * QSTR + kb));
                #pragma unroll
                for (int ni = 0; ni < 4; ni++) {
                    mma16(accS[mi][ni], ah, bh[ni]);
                    mma16(accS[mi][ni], ah, bl[ni]);
                    mma16(accS[mi][ni], al, bh[ni]);
                }
            }
        }
    };

    // ================= Pass 1: online row stats =================
    float mrun[8], srun[8];
    #pragma unroll
    for (int j = 0; j < 8; j++) { mrun[j] = -1e30f; srun[j] = 0.f; }

    loadQ(); loadK(0, 0); cp_commit();
    for (int kt = 0; kt < 16; kt++) {
        if (kt < 15) { loadK(kt + 1, (kt + 1) & 1); cp_commit(); cp_wait<1>(); }
        else         { cp_wait<0>(); }
        __syncthreads();
        computeS(kt & 1);
        #pragma unroll
        for (int mi = 0; mi < 4; mi++) {
            #pragma unroll
            for (int h = 0; h < 2; h++) {
                const int j = mi * 2 + h;
                float vv[8];
                #pragma unroll
                for (int ni = 0; ni < 4; ni++) {
                    vv[2*ni]   = accS[mi][ni][2*h]   * 0.125f;
                    vv[2*ni+1] = accS[mi][ni][2*h+1] * 0.125f;
                }
                float tm = vv[0];
                #pragma unroll
                for (int c = 1; c < 8; c++) tm = fmaxf(tm, vv[c]);
                float M = fmaxf(mrun[j], tm);
                float add = 0.f;
                #pragma unroll
                for (int c = 0; c < 8; c++) add += __expf(vv[c] - M);
                srun[j] = srun[j] * __expf(mrun[j] - M) + add;
                mrun[j] = M;
            }
        }
        __syncthreads();
    }

    // reduce across t lanes (4 lanes share a row)
    #pragma unroll
    for (int j = 0; j < 8; j++) {
        #pragma unroll
        for (int off = 1; off <= 2; off <<= 1) {
            float om = __shfl_xor_sync(0xffffffffu, mrun[j], off);
            float os = __shfl_xor_sync(0xffffffffu, srun[j], off);
            float M = fmaxf(mrun[j], om);
            srun[j] = srun[j] * __expf(mrun[j] - M) + os * __expf(om - M);
            mrun[j] = M;
        }
    }
    if (t == 0) {
        #pragma unroll
        for (int mi = 0; mi < 4; mi++)
            #pragma unroll
            for (int h = 0; h < 2; h++) {
                int row = wm * 64 + mi * 16 + g + h * 8;
                redm[wn * 128 + row] = mrun[mi * 2 + h];
                reds[wn * 128 + row] = srun[mi * 2 + h];
            }
    }
    __syncthreads();
    if (wn == 0 && t == 0) {
        #pragma unroll
        for (int mi = 0; mi < 4; mi++)
            #pragma unroll
            for (int h = 0; h < 2; h++) {
                int row = wm * 64 + mi * 16 + g + h * 8;
                float M = redm[row];
                #pragma unroll
                for (int w = 1; w < 4; w++) M = fmaxf(M, redm[w * 128 + row]);
                float S = 0.f;
                #pragma unroll
                for (int w = 0; w < 4; w++)
                    S += reds[w * 128 + row] * __expf(redm[w * 128 + row] - M);
                fm[row] = M;
                fi[row] = 1.f / S;
            }
    }
    __syncthreads();

    // ================= Pass 2: recompute, write p, O += P V =================
    float accO[4][2][4];
    #pragma unroll
    for (int mi = 0; mi < 4; mi++)
        #pragma unroll
        for (int ni = 0; ni < 2; ni++)
            #pragma unroll
            for (int r = 0; r < 4; r++) accO[mi][ni][r] = 0.f;

    loadK(0, 0); cp_commit();
    for (int kt = 0; kt < 16; kt++) {
        loadV(kt); cp_commit();
        cp_wait<1>();                 // K(kt) ready
        __syncthreads();
        if (kt < 15) { loadK(kt + 1, (kt + 1) & 1); cp_commit(); }

        computeS(kt & 1);

        // normalize, write p to attn, split into sP
        #pragma unroll
        for (int mi = 0; mi < 4; mi++) {
            const int r0 = wm * 64 + mi * 16 + g;
            const float m0 = fm[r0],     i0 = fi[r0];
            const float m1 = fm[r0 + 8], i1 = fi[r0 + 8];
            #pragma unroll
            for (int ni = 0; ni < 4; ni++) {
                const int cc = wn * 32 + ni * 8 + 2 * t;
                float p00 = __expf(accS[mi][ni][0] * 0.125f - m0) * i0;
                float p01 = __expf(accS[mi][ni][1] * 0.125f - m0) * i0;
                float p10 = __expf(accS[mi][ni][2] * 0.125f - m1) * i1;
                float p11 = __expf(accS[mi][ni][3] * 0.125f - m1) * i1;
                float2 o0 = {p00, p01}, o1 = {p10, p11};
                *(float2*)(attnZ + (long)r0 * 2048 + kt * 128 + cc)       = o0;
                *(float2*)(attnZ + (long)(r0 + 8) * 2048 + kt * 128 + cc) = o1;
                store_split2(sPh + r0 * VSTR + cc,       sPl + r0 * VSTR + cc,       p00, p01);
                store_split2(sPh + (r0 + 8) * VSTR + cc, sPl + (r0 + 8) * VSTR + cc, p10, p11);
            }
        }
        if (kt < 15) cp_wait<1>(); else cp_wait<0>();   // V(kt) ready
        __syncthreads();

        // O += P @ V  (k = 128, 8 k16 steps, 3-pass)
        #pragma unroll
        for (int ks = 0; ks < 8; ks++) {
            const int kb = ks * 16 + lkof;
            uint32_t bh[2][2], bl[2][2];
            {
                int n = wn * 16 + lrow;
                uint32_t r0, r1, r2, r3;
                ldmx4(r0, r1, r2, r3, smem_u32(sVh + n * VSTR + kb));
                bh[0][0] = r0; bh[1][0] = r1; bh[0][1] = r2; bh[1][1] = r3;
                ldmx4(r0, r1, r2, r3, smem_u32(sVl + n * VSTR + kb));
                bl[0][0] = r0; bl[1][0] = r1; bl[0][1] = r2; bl[1][1] = r3;
            }
            #pragma unroll
            for (int mi = 0; mi < 4; mi++) {
                int m = wm * 64 + mi * 16 + lrow;
                uint32_t ph[4], pl[4];
                ldmx4(ph[0], ph[1], ph[2], ph[3], smem_u32(sPh + m * VSTR + kb));
                ldmx4(pl[0], pl[1], pl[2], pl[3], smem_u32(sPl + m * VSTR + kb));
                #pragma unroll
                for (int ni = 0; ni < 2; ni++) {
                    mma16(accO[mi][ni], ph, bh[ni]);
                    mma16(accO[mi][ni], ph, bl[ni]);
                    mma16(accO[mi][ni], pl, bh[ni]);
                }
            }
        }
        __syncthreads();
    }

    // O epilogue -> split Oh/Ol
    __nv_bfloat16* Ohz = Oh + z * HEAD_STRIDE + (long)rb * 128 * 64;
    __nv_bfloat16* Olz = Ol + z * HEAD_STRIDE + (long)rb * 128 * 64;
    #pragma unroll
    for (int mi = 0; mi < 4; mi++) {
        #pragma unroll
        for (int ni = 0; ni < 2; ni++) {
            int r0 = wm * 64 + mi * 16 + g;
            int cc = wn * 16 + ni * 8 + 2 * t;
            store_split2(Ohz + (long)r0 * 64 + cc,       Olz + (long)r0 * 64 + cc,
                         accO[mi][ni][0], accO[mi][ni][1]);
            store_split2(Ohz + (long)(r0 + 8) * 64 + cc, Olz + (long)(r0 + 8) * 64 + cc,
                         accO[mi][ni][2], accO[mi][ni][3]);
        }
    }
}

// ---------------------------------------------------------------------------
extern "C" void kernel_launch(void* const* d_in, const int* in_sizes, int n_in,
                              void* d_out, int out_size)
{
    const float* pre_q = (const float*)d_in[0];
    const float* pre_k = (const float*)d_in[1];
    const float* pre_v = (const float*)d_in[2];
    const float* Wq = (const float*)d_in[3];
    const float* bq = (const float*)d_in[4];
    const float* Wk = (const float*)d_in[5];
    const float* bk = (const float*)d_in[6];
    const float* Wv = (const float*)d_in[7];
    const float* bv = (const float*)d_in[8];
    const float* Wo = (const float*)d_in[9];
    const float* bo = (const float*)d_in[10];

    float* proj = (float*)d_out;
    float* attn = proj + PROJ_ELEMS;

    __nv_bfloat16 *preh, *prel, *Wh, *Wl, *Woh, *Wol, *QKVh, *QKVl, *Vth, *Vtl, *Oh, *Ol;
    float* bias3;
    cudaGetSymbolAddress((void**)&preh, g_preh);
    cudaGetSymbolAddress((void**)&prel, g_prel);
    cudaGetSymbolAddress((void**)&Wh, g_Wh);
    cudaGetSymbolAddress((void**)&Wl, g_Wl);
    cudaGetSymbolAddress((void**)&Woh, g_Woh);
    cudaGetSymbolAddress((void**)&Wol, g_Wol);
    cudaGetSymbolAddress((void**)&bias3, g_bias3);
    cudaGetSymbolAddress((void**)&QKVh, g_QKVh);
    cudaGetSymbolAddress((void**)&QKVl, g_QKVl);
    cudaGetSymbolAddress((void**)&Vth, g_Vth);
    cudaGetSymbolAddress((void**)&Vtl, g_Vtl);
    cudaGetSymbolAddress((void**)&Oh, g_Oh);
    cudaGetSymbolAddress((void**)&Ol, g_Ol);

    static bool attr_done = false;
    if (!attr_done) {
        cudaFuncSetAttribute(gemm3<0>, cudaFuncAttributeMaxDynamicSharedMemorySize, 81920);
        cudaFuncSetAttribute(gemm3<1>, cudaFuncAttributeMaxDynamicSharedMemorySize, 81920);
        cudaFuncSetAttribute(fused_attn, cudaFuncAttributeMaxDynamicSharedMemorySize, 220160);
        attr_done = true;
    }

    // ---- prep: split inputs/weights; biases ----
    splitk<<<4096, 256>>>((const float4*)pre_q, preh,             prel,             1048576);
    splitk<<<4096, 256>>>((const float4*)pre_k, preh + 4194304,   prel + 4194304,   1048576);
    splitk<<<4096, 256>>>((const float4*)pre_v, preh + 8388608,   prel + 8388608,   1048576);
    splitk<<<1024, 256>>>((const float4*)Wq,    Wh,               Wl,               262144);
    splitk<<<1024, 256>>>((const float4*)Wk,    Wh + 1048576,     Wl + 1048576,     262144);
    splitk<<<1024, 256>>>((const float4*)Wv,    Wh + 2097152,     Wl + 2097152,     262144);
    splitk<<<1024, 256>>>((const float4*)Wo,    Woh,              Wol,              262144);
    biascopy<<<4, 256>>>(bq, bk, bv, bias3);

    // ---- QKV projections (merged z=3): split bf16 outputs ----
    gemm3<1><<<dim3(8, 32, 3), 256, 81920>>>(
        preh, prel, Wh, Wl, bias3, nullptr, QKVh, QKVl,
        4096, 1024, 1024, 1.f, 4194304, 1048576, 4194304, 1024);

    // ---- transpose V per head ----
    transposeV<<<dim3(32, 32), 256>>>(QKVh + 8388608, QKVl + 8388608, Vth, Vtl);

    // ---- fused scores + softmax + PV ----
    fused_attn<<<dim3(16, 32), 256, 220160>>>(QKVh, QKVl, Vth, Vtl, attn, Oh, Ol);

    // ---- output projection: proj = O @ Wo^T + bo ----
    gemm3<0><<<dim3(8, 32, 1), 256, 81920>>>(
        Oh, Ol, Woh, Wol, bo, proj, nullptr, nullptr,
        4096, 1024, 1024, 1.f, 0, 0, 0, 0);
}

// round 11
// speedup vs baseline: 1.1130x; 1.1130x over previous
#include <cuda_runtime.h>
#include <cuda_bf16.h>
#include <cstdint>

// Shapes (fixed): B=2, S=2048, D=1024, H=16, d=64
// head h of batch b = contiguous block (b*2048 + h*128)*1024 viewed as [2048,64] row-major
// d_out = [ proj : 4194304 f32 ][ attn : 134217728 f32 ]

#define PROJ_ELEMS 4194304LL
#define HEAD_STRIDE 131072LL
#define ATTN_STRIDE 4194304LL

// ---------------- persistent device-global scratch ----------------
__device__ __nv_bfloat16 g_preh[12582912], g_prel[12582912];   // pre_q|pre_k|pre_v
__device__ __nv_bfloat16 g_Wh[3145728],   g_Wl[3145728];       // Wq|Wk|Wv
__device__ __nv_bfloat16 g_Woh[1048576],  g_Wol[1048576];
__device__ float         g_bias3[3072];                        // bq|bk|bv
__device__ __nv_bfloat16 g_QKVh[12582912], g_QKVl[12582912];   // Q|K|V (hi/lo)
__device__ __nv_bfloat16 g_Vth[4194304],  g_Vtl[4194304];      // V transposed [head][64][2048]
__device__ __nv_bfloat16 g_Oh[4194304],   g_Ol[4194304];
__device__ float g_sm[16777216];   // per (head, row, colTile) tile row-max   [32][2048][16]
__device__ float g_ss[16777216];   // per (head, row, colTile) tile expsum

// ---------------- helpers ----------------
__device__ __forceinline__ uint32_t smem_u32(const void* p) {
    return (uint32_t)__cvta_generic_to_shared(p);
}
__device__ __forceinline__ void cpa16(__nv_bfloat16* s, const __nv_bfloat16* g) {
    asm volatile("cp.async.cg.shared.global [%0], [%1], 16;"
                 :: "r"(smem_u32(s)), "l"(__cvta_generic_to_global(g)));
}
__device__ __forceinline__ void cp_commit() { asm volatile("cp.async.commit_group;"); }
template<int NW> __device__ __forceinline__ void cp_wait() {
    asm volatile("cp.async.wait_group %0;" :: "n"(NW));
}
__device__ __forceinline__ void ldmx4(uint32_t& r0, uint32_t& r1, uint32_t& r2, uint32_t& r3,
                                      uint32_t addr) {
    asm volatile("ldmatrix.sync.aligned.m8n8.x4.shared.b16 {%0,%1,%2,%3}, [%4];"
                 : "=r"(r0), "=r"(r1), "=r"(r2), "=r"(r3) : "r"(addr));
}
__device__ __forceinline__ void mma16(float* c, const uint32_t* a, const uint32_t* b) {
    asm volatile(
        "mma.sync.aligned.m16n8k16.row.col.f32.bf16.bf16.f32 "
        "{%0,%1,%2,%3},{%4,%5,%6,%7},{%8,%9},{%0,%1,%2,%3};"
        : "+f"(c[0]), "+f"(c[1]), "+f"(c[2]), "+f"(c[3])
        : "r"(a[0]), "r"(a[1]), "r"(a[2]), "r"(a[3]), "r"(b[0]), "r"(b[1]));
}
__device__ __forceinline__ void store_split2(__nv_bfloat16* h, __nv_bfloat16* l,
                                             float a, float b) {
    __nv_bfloat16 ha = __float2bfloat16(a), hb = __float2bfloat16(b);
    __nv_bfloat16 la = __float2bfloat16(a - __bfloat162float(ha));
    __nv_bfloat16 lb = __float2bfloat16(b - __bfloat162float(hb));
    __nv_bfloat162 hp; hp.x = ha; hp.y = hb;
    __nv_bfloat162 lp; lp.x = la; lp.y = lb;
    *(__nv_bfloat162*)h = hp;
    *(__nv_bfloat162*)l = lp;
}

#define SPAD 40   // smem row stride (bf16) -> conflict-free ldmatrix

// ---------------------------------------------------------------------------
// prep: all 7 fp32->bf16(hi,lo) splits in ONE launch (grid.y selects tensor)
// ---------------------------------------------------------------------------
struct SJob { const float4* s; __nv_bfloat16* h; __nv_bfloat16* l; int n4; };
struct SJobs { SJob j[7]; };

__global__ void splitk_all(SJobs js)
{
    SJob jb = js.j[blockIdx.y];
    int i = blockIdx.x * blockDim.x + threadIdx.x;
    if (i >= jb.n4) return;
    float4 v = jb.s[i];
    float vs[4] = {v.x, v.y, v.z, v.w};
    __nv_bfloat16 hh[4], ll[4];
    #pragma unroll
    for (int c = 0; c < 4; c++) {
        hh[c] = __float2bfloat16(vs[c]);
        ll[c] = __float2bfloat16(vs[c] - __bfloat162float(hh[c]));
    }
    __nv_bfloat162 h0; h0.x = hh[0]; h0.y = hh[1];
    __nv_bfloat162 h1; h1.x = hh[2]; h1.y = hh[3];
    __nv_bfloat162 l0; l0.x = ll[0]; l0.y = ll[1];
    __nv_bfloat162 l1; l1.x = ll[2]; l1.y = ll[3];
    *(__nv_bfloat162*)(jb.h + 4 * i)     = h0;
    *(__nv_bfloat162*)(jb.h + 4 * i + 2) = h1;
    *(__nv_bfloat162*)(jb.l + 4 * i)     = l0;
    *(__nv_bfloat162*)(jb.l + 4 * i + 2) = l1;
}

__global__ void biascopy(const float* __restrict__ bq, const float* __restrict__ bk,
                         const float* __restrict__ bv, float* __restrict__ dst)
{
    int i = blockIdx.x * blockDim.x + threadIdx.x;
    if (i < 1024) { dst[i] = bq[i]; dst[1024 + i] = bk[i]; dst[2048 + i] = bv[i]; }
}

// Transpose V per head: [2048,64] -> [64,2048], hi and lo.
__global__ __launch_bounds__(256) void transposeV(
    const __nv_bfloat16* __restrict__ Vh, const __nv_bfloat16* __restrict__ Vl,
    __nv_bfloat16* __restrict__ Vth, __nv_bfloat16* __restrict__ Vtl)
{
    __shared__ __nv_bfloat16 th[64][72], tl[64][72];
    const long head = blockIdx.y;
    const int  k0   = blockIdx.x * 64;
    const __nv_bfloat16* inh = Vh + head * HEAD_STRIDE + (long)k0 * 64;
    const __nv_bfloat16* inl = Vl + head * HEAD_STRIDE + (long)k0 * 64;
    __nv_bfloat16* outh = Vth + head * HEAD_STRIDE + k0;
    __nv_bfloat16* outl = Vtl + head * HEAD_STRIDE + k0;

    const int tid = threadIdx.x;
    const int lr = tid >> 2, seg = tid & 3;
    #pragma unroll
    for (int i = 0; i < 2; i++) {
        int col = seg * 16 + i * 8;
        *(uint4*)&th[lr][col] = *(const uint4*)(inh + (long)lr * 64 + col);
        *(uint4*)&tl[lr][col] = *(const uint4*)(inl + (long)lr * 64 + col);
    }
    __syncthreads();
    #pragma unroll
    for (int i = 0; i < 2; i++) {
        int kk = seg * 16 + i * 8;
        __nv_bfloat16 eh[8], el[8];
        #pragma unroll
        for (int j = 0; j < 8; j++) { eh[j] = th[kk + j][lr]; el[j] = tl[kk + j][lr]; }
        *(uint4*)(outh + (long)lr * 2048 + kk) = *(uint4*)eh;
        *(uint4*)(outl + (long)lr * 2048 + kk) = *(uint4*)el;
    }
}

// ---------------------------------------------------------------------------
// gemm3: 3-pass split-bf16 NT GEMM, cp.async 2-stage pipelined.
//   EPI=0: fp32 C (+bias).
//   EPI=1: split bf16 (Ch,Cl) (+bias).
//   EPI=2: fp32 C + per-tile row softmax stats (max, expsum) -> smOut/ssOut.
// Block 128x128, BK=32, 256 threads, warp tile 64x32. dyn smem 81920B.
// ---------------------------------------------------------------------------
template<int EPI>
__global__ __launch_bounds__(256) void gemm3(
    const __nv_bfloat16* __restrict__ Ah, const __nv_bfloat16* __restrict__ Al,
    const __nv_bfloat16* __restrict__ Bh, const __nv_bfloat16* __restrict__ Bl,
    const float* __restrict__ bias, float* __restrict__ C,
    __nv_bfloat16* __restrict__ Ch, __nv_bfloat16* __restrict__ Cl,
    int M, int N, int K, float alpha,
    long zsA, long zsB, long zsC, int zsBias,
    float* __restrict__ smOut, float* __restrict__ ssOut)
{
    extern __shared__ __align__(16) __nv_bfloat16 sm[];
    const long z = blockIdx.z;
    Ah += z * zsA; Al += z * zsA;
    Bh += z * zsB; Bl += z * zsB;
    const float* bz = bias ? bias + (long)z * zsBias : nullptr;

    const int tid = threadIdx.x, warp = tid >> 5, lane = tid & 31;
    const int g = lane >> 2, t = lane & 3, wm = warp >> 2, wn = warp & 3;
    const int lrow = lane & 15, lkof = (lane & 16) >> 1;
    const int rowC = blockIdx.y * 128, colC = blockIdx.x * 128;

    const __nv_bfloat16* srcs[4] = { Ah + (long)rowC * K, Al + (long)rowC * K,
                                     Bh + (long)colC * K, Bl + (long)colC * K };

    float acc[4][4][4];
    #pragma unroll
    for (int mi = 0; mi < 4; mi++)
        #pragma unroll
        for (int ni = 0; ni < 4; ni++)
            #pragma unroll
            for (int r = 0; r < 4; r++) acc[mi][ni][r] = 0.f;

    const int rr0 = tid >> 2,            ss0 = tid & 3;
    const int rr1 = (tid + 256) >> 2,    ss1 = (tid + 256) & 3;

    auto load_stage = [&](int stg, int k0) {
        __nv_bfloat16* base = sm + stg * 4 * (128 * SPAD);
        #pragma unroll
        for (int m = 0; m < 4; m++) {
            __nv_bfloat16* d = base + m * (128 * SPAD);
            cpa16(d + rr0 * SPAD + ss0 * 8, srcs[m] + (long)rr0 * K + k0 + ss0 * 8);
            cpa16(d + rr1 * SPAD + ss1 * 8, srcs[m] + (long)rr1 * K + k0 + ss1 * 8);
        }
    };

    auto compute = [&](int stg) {
        const __nv_bfloat16* bAh = sm + (stg * 4 + 0) * (128 * SPAD);
        const __nv_bfloat16* bAl = sm + (stg * 4 + 1) * (128 * SPAD);
        const __nv_bfloat16* bBh = sm + (stg * 4 + 2) * (128 * SPAD);
        const __nv_bfloat16* bBl = sm + (stg * 4 + 3) * (128 * SPAD);
        #pragma unroll
        for (int ks = 0; ks < 2; ks++) {
            const int kb = ks * 16 + lkof;
            uint32_t bh[4][2], bl[4][2];
            #pragma unroll
            for (int p = 0; p < 2; p++) {
                int n = wn * 32 + p * 16 + lrow;
                uint32_t r0, r1, r2, r3;
                ldmx4(r0, r1, r2, r3, smem_u32(bBh + n * SPAD + kb));
                bh[2*p][0] = r0; bh[2*p+1][0] = r1; bh[2*p][1] = r2; bh[2*p+1][1] = r3;
                ldmx4(r0, r1, r2, r3, smem_u32(bBl + n * SPAD + kb));
                bl[2*p][0] = r0; bl[2*p+1][0] = r1; bl[2*p][1] = r2; bl[2*p+1][1] = r3;
            }
            #pragma unroll
            for (int mi = 0; mi < 4; mi++) {
                int mrow = wm * 64 + mi * 16 + lrow;
                uint32_t ah[4], al[4];
                ldmx4(ah[0], ah[1], ah[2], ah[3], smem_u32(bAh + mrow * SPAD + kb));
                ldmx4(al[0], al[1], al[2], al[3], smem_u32(bAl + mrow * SPAD + kb));
                #pragma unroll
                for (int ni = 0; ni < 4; ni++) {
                    mma16(acc[mi][ni], ah, bh[ni]);
                    mma16(acc[mi][ni], ah, bl[ni]);
                    mma16(acc[mi][ni], al, bh[ni]);
                }
            }
        }
    };

    const int KT = K >> 5;
    load_stage(0, 0); cp_commit();
    for (int kt = 0; kt < KT; kt++) {
        if (kt + 1 < KT) { load_stage((kt + 1) & 1, (kt + 1) * 32); cp_commit(); cp_wait<1>(); }
        else             { cp_wait<0>(); }
        __syncthreads();
        compute(kt & 1);
        __syncthreads();
    }

    float*         Cz  = (EPI != 1) ? C  + z * zsC : nullptr;
    __nv_bfloat16* Chz = (EPI == 1) ? Ch + z * zsC : nullptr;
    __nv_bfloat16* Clz = (EPI == 1) ? Cl + z * zsC : nullptr;

    #pragma unroll
    for (int mi = 0; mi < 4; mi++) {
        #pragma unroll
        for (int ni = 0; ni < 4; ni++) {
            int r0 = rowC + wm * 64 + mi * 16 + g;
            int cc = colC + wn * 32 + ni * 8 + 2 * t;
            float b0 = bz ? bz[cc] : 0.f, b1 = bz ? bz[cc + 1] : 0.f;
            float c00 = fmaf(acc[mi][ni][0], alpha, b0);
            float c01 = fmaf(acc[mi][ni][1], alpha, b1);
            float c10 = fmaf(acc[mi][ni][2], alpha, b0);
            float c11 = fmaf(acc[mi][ni][3], alpha, b1);
            if (EPI != 1) {
                float2 o0 = {c00, c01}, o1 = {c10, c11};
                *(float2*)(Cz + (long)r0 * N + cc)       = o0;
                *(float2*)(Cz + (long)(r0 + 8) * N + cc) = o1;
            } else {
                store_split2(Chz + (long)r0 * N + cc,       Clz + (long)r0 * N + cc,       c00, c01);
                store_split2(Chz + (long)(r0 + 8) * N + cc, Clz + (long)(r0 + 8) * N + cc, c10, c11);
            }
        }
    }

    if constexpr (EPI == 2) {
        // per-tile row stats: max + expsum vs that max, reduced over 8 cols/thread,
        // then 4 t-lanes, then 4 wn warps via smem.
        __shared__ float redm[4][128];
        __shared__ float reds[4][128];
        float myM[8], myS[8];
        #pragma unroll
        for (int mi = 0; mi < 4; mi++) {
            #pragma unroll
            for (int h = 0; h < 2; h++) {
                float vv[8];
                #pragma unroll
                for (int ni = 0; ni < 4; ni++) {
                    vv[2*ni]   = acc[mi][ni][2*h]   * alpha;
                    vv[2*ni+1] = acc[mi][ni][2*h+1] * alpha;
                }
                float tm = vv[0];
                #pragma unroll
                for (int c = 1; c < 8; c++) tm = fmaxf(tm, vv[c]);
                float ts = 0.f;
                #pragma unroll
                for (int c = 0; c < 8; c++) ts += __expf(vv[c] - tm);
                #pragma unroll
                for (int off = 1; off <= 2; off <<= 1) {
                    float om = __shfl_xor_sync(0xffffffffu, tm, off);
                    float os = __shfl_xor_sync(0xffffffffu, ts, off);
                    float M = fmaxf(tm, om);
                    ts = ts * __expf(tm - M) + os * __expf(om - M);
                    tm = M;
                }
                myM[mi*2+h] = tm; myS[mi*2+h] = ts;
            }
        }
        if (t == 0) {
            #pragma unroll
            for (int mi = 0; mi < 4; mi++)
                #pragma unroll
                for (int h = 0; h < 2; h++) {
                    int row = wm * 64 + mi * 16 + g + h * 8;
                    redm[wn][row] = myM[mi*2+h];
                    reds[wn][row] = myS[mi*2+h];
                }
        }
        __syncthreads();
        if (wn == 0 && t == 0) {
            #pragma unroll
            for (int mi = 0; mi < 4; mi++)
                #pragma unroll
                for (int h = 0; h < 2; h++) {
                    int row = wm * 64 + mi * 16 + g + h * 8;
                    float M = redm[0][row];
                    #pragma unroll
                    for (int w = 1; w < 4; w++) M = fmaxf(M, redm[w][row]);
                    float S = 0.f;
                    #pragma unroll
                    for (int w = 0; w < 4; w++)
                        S += reds[w][row] * __expf(redm[w][row] - M);
                    long idx = (((long)z * 2048) + (rowC + row)) * 16 + blockIdx.x;
                    smOut[idx] = M;
                    ssOut[idx] = S;
                }
        }
    }
}

// ---------------------------------------------------------------------------
// gemm_pv: fused softmax-normalize + (P @ V) per (b,h).
//   Reads raw scores s from attn region, prologue folds 16 tile-stats/row,
//   fill path computes p=exp(s-m)*inv, WRITES p back to attn (the output),
//   splits p to bf16 hi/lo in smem, 3-pass MMA against pre-split V^T.
// Block 128x64, BK=32, 256 thr. dyn smem 61440B + 1KB static.
// ---------------------------------------------------------------------------
__global__ __launch_bounds__(256) void gemm_pv(
    float* __restrict__ attn,
    const __nv_bfloat16* __restrict__ Vth, const __nv_bfloat16* __restrict__ Vtl,
    __nv_bfloat16* __restrict__ Oh, __nv_bfloat16* __restrict__ Ol,
    const float* __restrict__ gsm, const float* __restrict__ gss)
{
    extern __shared__ __align__(16) __nv_bfloat16 smb[];
    __nv_bfloat16* sPh = smb;                       // [2][128*SPAD]
    __nv_bfloat16* sPl = smb + 2 * 128 * SPAD;
    __nv_bfloat16* sVh = smb + 4 * 128 * SPAD;      // [2][64*SPAD]
    __nv_bfloat16* sVl = smb + 4 * 128 * SPAD + 2 * 64 * SPAD;
    __shared__ float sfm[128], sfi[128];

    const long z = blockIdx.z;
    const int  rb = blockIdx.y;
    float* Pp = attn + z * ATTN_STRIDE + (long)rb * 128 * 2048;
    const __nv_bfloat16* Vh = Vth + z * HEAD_STRIDE;
    const __nv_bfloat16* Vl = Vtl + z * HEAD_STRIDE;
    __nv_bfloat16* Ohz = Oh + z * HEAD_STRIDE + (long)rb * 128 * 64;
    __nv_bfloat16* Olz = Ol + z * HEAD_STRIDE + (long)rb * 128 * 64;

    const int tid = threadIdx.x, warp = tid >> 5, lane = tid & 31;
    const int g = lane >> 2, t = lane & 3, wm = warp >> 2, wn = warp & 3;
    const int lrow = lane & 15, lkof = (lane & 16) >> 1;

    // ---- stats prologue: combine 16 tile stats per row ----
    if (tid < 128) {
        int rowg = rb * 128 + tid;
        const float* pm = gsm + ((((long)z * 2048) + rowg) << 4);
        const float* ps = gss + ((((long)z * 2048) + rowg) << 4);
        float M = pm[0];
        #pragma unroll
        for (int ct = 1; ct < 16; ct++) M = fmaxf(M, pm[ct]);
        float S = 0.f;
        #pragma unroll
        for (int ct = 0; ct < 16; ct++) S += ps[ct] * __expf(pm[ct] - M);
        sfm[tid] = M;
        sfi[tid] = 1.f / S;
    }
    __syncthreads();

    float acc[4][2][4];
    #pragma unroll
    for (int mi = 0; mi < 4; mi++)
        #pragma unroll
        for (int ni = 0; ni < 2; ni++)
            #pragma unroll
            for (int r = 0; r < 4; r++) acc[mi][ni][r] = 0.f;

    const int pr = tid >> 3, ps8 = tid & 7;         // P: rows pr+32i, 16B segs
    const int nr = tid >> 2, ns = tid & 3;          // V: row nr, seg ns

    float fmr[4], fir[4];
    #pragma unroll
    for (int i = 0; i < 4; i++) { fmr[i] = sfm[pr + i * 32]; fir[i] = sfi[pr + i * 32]; }

    float4 pregs[4];
    auto ldP = [&](int k0) {
        #pragma unroll
        for (int i = 0; i < 4; i++) {
            int lr = pr + i * 32;
            pregs[i] = *(const float4*)(Pp + (long)lr * 2048 + k0 + ps8 * 4);
        }
    };
    auto stsP = [&](int stg, int k0) {
        __nv_bfloat16* dh = sPh + stg * 128 * SPAD;
        __nv_bfloat16* dl = sPl + stg * 128 * SPAD;
        #pragma unroll
        for (int i = 0; i < 4; i++) {
            int lr = pr + i * 32;
            float vals[4] = {pregs[i].x, pregs[i].y, pregs[i].z, pregs[i].w};
            float pv[4];
            #pragma unroll
            for (int c = 0; c < 4; c++)
                pv[c] = __expf(vals[c] - fmr[i]) * fir[i];
            float4 o = {pv[0], pv[1], pv[2], pv[3]};
            *(float4*)(Pp + (long)lr * 2048 + k0 + ps8 * 4) = o;   // normalized attn out
            #pragma unroll
            for (int c = 0; c < 4; c++) {
                __nv_bfloat16 h = __float2bfloat16(pv[c]);
                __nv_bfloat16 l = __float2bfloat16(pv[c] - __bfloat162float(h));
                dh[lr * SPAD + ps8 * 4 + c] = h;
                dl[lr * SPAD + ps8 * 4 + c] = l;
            }
        }
    };
    auto loadV = [&](int stg, int k0) {
        cpa16(sVh + stg * 64 * SPAD + nr * SPAD + ns * 8, Vh + (long)nr * 2048 + k0 + ns * 8);
        cpa16(sVl + stg * 64 * SPAD + nr * SPAD + ns * 8, Vl + (long)nr * 2048 + k0 + ns * 8);
    };

    auto compute = [&](int stg) {
        const __nv_bfloat16* bPh = sPh + stg * 128 * SPAD;
        const __nv_bfloat16* bPl = sPl + stg * 128 * SPAD;
        const __nv_bfloat16* bVh = sVh + stg * 64 * SPAD;
        const __nv_bfloat16* bVl = sVl + stg * 64 * SPAD;
        #pragma unroll
        for (int ks = 0; ks < 2; ks++) {
            const int kb = ks * 16 + lkof;
            uint32_t bh[2][2], bl[2][2];
            {
                int n = wn * 16 + lrow;
                uint32_t r0, r1, r2, r3;
                ldmx4(r0, r1, r2, r3, smem_u32(bVh + n * SPAD + kb));
                bh[0][0] = r0; bh[1][0] = r1; bh[0][1] = r2; bh[1][1] = r3;
                ldmx4(r0, r1, r2, r3, smem_u32(bVl + n * SPAD + kb));
                bl[0][0] = r0; bl[1][0] = r1; bl[0][1] = r2; bl[1][1] = r3;
            }
            #pragma unroll
            for (int mi = 0; mi < 4; mi++) {
                int m = wm * 64 + mi * 16 + lrow;
                uint32_t ph[4], pl[4];
                ldmx4(ph[0], ph[1], ph[2], ph[3], smem_u32(bPh + m * SPAD + kb));
                ldmx4(pl[0], pl[1], pl[2], pl[3], smem_u32(bPl + m * SPAD + kb));
                #pragma unroll
                for (int ni = 0; ni < 2; ni++) {
                    mma16(acc[mi][ni], ph, bh[ni]);
                    mma16(acc[mi][ni], ph, bl[ni]);
                    mma16(acc[mi][ni], pl, bh[ni]);
                }
            }
        }
    };

    ldP(0);
    loadV(0, 0); cp_commit();
    for (int kt = 0; kt < 64; kt++) {
        stsP(kt & 1, kt * 32);
        cp_wait<0>();
        __syncthreads();
        if (kt + 1 < 64) {
            ldP((kt + 1) * 32);
            loadV((kt + 1) & 1, (kt + 1) * 32); cp_commit();
        }
        compute(kt & 1);
        __syncthreads();
    }

    #pragma unroll
    for (int mi = 0; mi < 4; mi++) {
        #pragma unroll
        for (int ni = 0; ni < 2; ni++) {
            int r0 = wm * 64 + mi * 16 + g;
            int cc = wn * 16 + ni * 8 + 2 * t;
            store_split2(Ohz + (long)r0 * 64 + cc,       Olz + (long)r0 * 64 + cc,
                         acc[mi][ni][0], acc[mi][ni][1]);
            store_split2(Ohz + (long)(r0 + 8) * 64 + cc, Olz + (long)(r0 + 8) * 64 + cc,
                         acc[mi][ni][2], acc[mi][ni][3]);
        }
    }
}

// ---------------------------------------------------------------------------
extern "C" void kernel_launch(void* const* d_in, const int* in_sizes, int n_in,
                              void* d_out, int out_size)
{
    const float* pre_q = (const float*)d_in[0];
    const float* pre_k = (const float*)d_in[1];
    const float* pre_v = (const float*)d_in[2];
    const float* Wq = (const float*)d_in[3];
    const float* bq = (const float*)d_in[4];
    const float* Wk = (const float*)d_in[5];
    const float* bk = (const float*)d_in[6];
    const float* Wv = (const float*)d_in[7];
    const float* bv = (const float*)d_in[8];
    const float* Wo = (const float*)d_in[9];
    const float* bo = (const float*)d_in[10];

    float* proj = (float*)d_out;
    float* attn = proj + PROJ_ELEMS;

    __nv_bfloat16 *preh, *prel, *Wh, *Wl, *Woh, *Wol, *QKVh, *QKVl, *Vth, *Vtl, *Oh, *Ol;
    float *bias3, *smp, *ssp;
    cudaGetSymbolAddress((void**)&preh, g_preh);
    cudaGetSymbolAddress((void**)&prel, g_prel);
    cudaGetSymbolAddress((void**)&Wh, g_Wh);
    cudaGetSymbolAddress((void**)&Wl, g_Wl);
    cudaGetSymbolAddress((void**)&Woh, g_Woh);
    cudaGetSymbolAddress((void**)&Wol, g_Wol);
    cudaGetSymbolAddress((void**)&bias3, g_bias3);
    cudaGetSymbolAddress((void**)&QKVh, g_QKVh);
    cudaGetSymbolAddress((void**)&QKVl, g_QKVl);
    cudaGetSymbolAddress((void**)&Vth, g_Vth);
    cudaGetSymbolAddress((void**)&Vtl, g_Vtl);
    cudaGetSymbolAddress((void**)&Oh, g_Oh);
    cudaGetSymbolAddress((void**)&Ol, g_Ol);
    cudaGetSymbolAddress((void**)&smp, g_sm);
    cudaGetSymbolAddress((void**)&ssp, g_ss);

    static bool attr_done = false;
    if (!attr_done) {
        cudaFuncSetAttribute(gemm3<0>, cudaFuncAttributeMaxDynamicSharedMemorySize, 81920);
        cudaFuncSetAttribute(gemm3<1>, cudaFuncAttributeMaxDynamicSharedMemorySize, 81920);
        cudaFuncSetAttribute(gemm3<2>, cudaFuncAttributeMaxDynamicSharedMemorySize, 81920);
        cudaFuncSetAttribute(gemm_pv,  cudaFuncAttributeMaxDynamicSharedMemorySize, 61440);
        attr_done = true;
    }

    // launch 0: biases
    biascopy<<<4, 256>>>(bq, bk, bv, bias3);

    // launch 1: all 7 splits in one kernel
    SJobs js;
    js.j[0] = { (const float4*)pre_q, preh,           prel,           1048576 };
    js.j[1] = { (const float4*)pre_k, preh + 4194304, prel + 4194304, 1048576 };
    js.j[2] = { (const float4*)pre_v, preh + 8388608, prel + 8388608, 1048576 };
    js.j[3] = { (const float4*)Wq,    Wh,             Wl,             262144 };
    js.j[4] = { (const float4*)Wk,    Wh + 1048576,   Wl + 1048576,   262144 };
    js.j[5] = { (const float4*)Wv,    Wh + 2097152,   Wl + 2097152,   262144 };
    js.j[6] = { (const float4*)Wo,    Woh,            Wol,            262144 };
    splitk_all<<<dim3(4096, 7), 256>>>(js);

    // launch 2: QKV projections (merged z=3), split bf16 outputs
    gemm3<1><<<dim3(8, 32, 3), 256, 81920>>>(
        preh, prel, Wh, Wl, bias3, nullptr, QKVh, QKVl,
        4096, 1024, 1024, 1.f, 4194304, 1048576, 4194304, 1024, nullptr, nullptr);

    // launch 3: transpose V per head
    transposeV<<<dim3(32, 32), 256>>>(QKVh + 8388608, QKVl + 8388608, Vth, Vtl);

    // launch 4: scores + per-tile stats
    gemm3<2><<<dim3(16, 16, 32), 256, 81920>>>(
        QKVh, QKVl, QKVh + 4194304, QKVl + 4194304, nullptr, attn, nullptr, nullptr,
        2048, 2048, 64, 0.125f, HEAD_STRIDE, HEAD_STRIDE, ATTN_STRIDE, 0, smp, ssp);

    // launch 5: fused softmax-normalize + P@V (writes normalized attn)
    gemm_pv<<<dim3(1, 16, 32), 256, 61440>>>(attn, Vth, Vtl, Oh, Ol, smp, ssp);

    // launch 6: output projection
    gemm3<0><<<dim3(8, 32, 1), 256, 81920>>>(
        Oh, Ol, Woh, Wol, bo, proj, nullptr, nullptr,
        4096, 1024, 1024, 1.f, 0, 0, 0, 0, nullptr, nullptr);
}

// round 13
// speedup vs baseline: 1.6706x; 1.5010x over previous
#include <cuda_runtime.h>
#include <cuda_fp16.h>
#include <cstdint>

// Shapes (fixed): B=2, S=2048, D=1024, H=16, d=64
// head h of batch b = contiguous block (b*2048 + h*128)*1024 viewed as [2048,64] row-major
// d_out = [ proj : 4194304 f32 ][ attn : 134217728 f32 ]

#define PROJ_ELEMS 4194304LL
#define HEAD_STRIDE 131072LL
#define ATTN_STRIDE 4194304LL

// ---------------- persistent device-global scratch (fp16 operands) ----------------
__device__ __half g_pre16[12582912];   // pre_q|pre_k|pre_v
__device__ __half g_W16[3145728];      // Wq|Wk|Wv
__device__ __half g_Wo16[1048576];
__device__ float  g_bias3[3072];       // bq|bk|bv
__device__ __half g_QKV16[12582912];   // Q|K|V
__device__ __half g_Vt16[4194304];     // V transposed [head][64][2048]
__device__ __half g_O16[4194304];
__device__ float  g_sm[1048576];       // per (head,row,colTile) tile row-max [32][2048][16]
__device__ float  g_ss[1048576];       // per (head,row,colTile) tile expsum

// ---------------- helpers ----------------
__device__ __forceinline__ uint32_t smem_u32(const void* p) {
    return (uint32_t)__cvta_generic_to_shared(p);
}
__device__ __forceinline__ void cpa16(void* s, const void* g) {
    asm volatile("cp.async.cg.shared.global [%0], [%1], 16;"
                 :: "r"(smem_u32(s)), "l"(__cvta_generic_to_global(g)));
}
__device__ __forceinline__ void cp_commit() { asm volatile("cp.async.commit_group;"); }
template<int NW> __device__ __forceinline__ void cp_wait() {
    asm volatile("cp.async.wait_group %0;" :: "n"(NW));
}
__device__ __forceinline__ void ldmx4(uint32_t& r0, uint32_t& r1, uint32_t& r2, uint32_t& r3,
                                      uint32_t addr) {
    asm volatile("ldmatrix.sync.aligned.m8n8.x4.shared.b16 {%0,%1,%2,%3}, [%4];"
                 : "=r"(r0), "=r"(r1), "=r"(r2), "=r"(r3) : "r"(addr));
}
__device__ __forceinline__ void mma16h(float* c, const uint32_t* a, const uint32_t* b) {
    asm volatile(
        "mma.sync.aligned.m16n8k16.row.col.f32.f16.f16.f32 "
        "{%0,%1,%2,%3},{%4,%5,%6,%7},{%8,%9},{%0,%1,%2,%3};"
        : "+f"(c[0]), "+f"(c[1]), "+f"(c[2]), "+f"(c[3])
        : "r"(a[0]), "r"(a[1]), "r"(a[2]), "r"(a[3]), "r"(b[0]), "r"(b[1]));
}

#define SPAD 40   // smem row stride (halves): 32 data + 8 pad -> conflict-free ldmatrix

// ---------------------------------------------------------------------------
// prep: all 7 fp32->fp16 conversions in ONE launch
// ---------------------------------------------------------------------------
struct CJob { const float4* s; __half* h; int n4; };
struct CJobs { CJob j[7]; };

__global__ void cvt_all(CJobs js)
{
    CJob jb = js.j[blockIdx.y];
    int i = blockIdx.x * blockDim.x + threadIdx.x;
    if (i >= jb.n4) return;
    float4 v = jb.s[i];
    __half2 a = __floats2half2_rn(v.x, v.y);
    __half2 b = __floats2half2_rn(v.z, v.w);
    *(__half2*)(jb.h + 4 * i)     = a;
    *(__half2*)(jb.h + 4 * i + 2) = b;
}

__global__ void biascopy(const float* __restrict__ bq, const float* __restrict__ bk,
                         const float* __restrict__ bv, float* __restrict__ dst)
{
    int i = blockIdx.x * blockDim.x + threadIdx.x;
    if (i < 1024) { dst[i] = bq[i]; dst[1024 + i] = bk[i]; dst[2048 + i] = bv[i]; }
}

// Transpose V per head: [2048,64] -> [64,2048].
__global__ __launch_bounds__(256) void transposeV(
    const __half* __restrict__ V, __half* __restrict__ Vt)
{
    __shared__ __half th[64][72];
    const long head = blockIdx.y;
    const int  k0   = blockIdx.x * 64;
    const __half* in = V + head * HEAD_STRIDE + (long)k0 * 64;
    __half* out = Vt + head * HEAD_STRIDE + k0;

    const int tid = threadIdx.x;
    const int lr = tid >> 2, seg = tid & 3;
    #pragma unroll
    for (int i = 0; i < 2; i++) {
        int col = seg * 16 + i * 8;
        *(uint4*)&th[lr][col] = *(const uint4*)(in + (long)lr * 64 + col);
    }
    __syncthreads();
    #pragma unroll
    for (int i = 0; i < 2; i++) {
        int kk = seg * 16 + i * 8;
        __half e[8];
        #pragma unroll
        for (int j = 0; j < 8; j++) e[j] = th[kk + j][lr];
        *(uint4*)(out + (long)lr * 2048 + kk) = *(uint4*)e;
    }
}

// ---------------------------------------------------------------------------
// gemm1: 1-pass fp16 NT GEMM (fp32 accumulate), cp.async 2-stage pipelined.
//   C[m,n] = alpha * sum_k A[m,k]*B[n,k] (+bias[n])
//   EPI=0: fp32 C.  EPI=1: fp16 C.  EPI=2: fp32 C + per-tile row stats.
// Block 128x128, BK=32, 256 threads (8 warps 2x4), warp tile 64x32.
// dyn smem = 2 stages * 2 matrices * 128*SPAD halves = 40960 B.
// ---------------------------------------------------------------------------
template<int EPI>
__global__ __launch_bounds__(256) void gemm1(
    const __half* __restrict__ A, const __half* __restrict__ B,
    const float* __restrict__ bias, float* __restrict__ C, __half* __restrict__ Cf,
    int M, int N, int K, float alpha,
    long zsA, long zsB, long zsC, int zsBias,
    float* __restrict__ smOut, float* __restrict__ ssOut)
{
    extern __shared__ __align__(16) __half sm[];
    const long z = blockIdx.z;
    A += z * zsA; B += z * zsB;
    const float* bz = bias ? bias + (long)z * zsBias : nullptr;

    const int tid = threadIdx.x, warp = tid >> 5, lane = tid & 31;
    const int g = lane >> 2, t = lane & 3, wm = warp >> 2, wn = warp & 3;
    const int lrow = lane & 15, lkof = (lane & 16) >> 1;
    const int rowC = blockIdx.y * 128, colC = blockIdx.x * 128;

    const __half* Ap = A + (long)rowC * K;
    const __half* Bp = B + (long)colC * K;

    float acc[4][4][4];
    #pragma unroll
    for (int mi = 0; mi < 4; mi++)
        #pragma unroll
        for (int ni = 0; ni < 4; ni++)
            #pragma unroll
            for (int r = 0; r < 4; r++) acc[mi][ni][r] = 0.f;

    const int rr = tid >> 2, ss = tid & 3;

    auto load_stage = [&](int stg, int k0) {
        __half* dA = sm + stg * 2 * (128 * SPAD);
        __half* dB = dA + 128 * SPAD;
        cpa16(dA + rr * SPAD + ss * 8,          Ap + (long)rr * K + k0 + ss * 8);
        cpa16(dA + (rr + 64) * SPAD + ss * 8,   Ap + (long)(rr + 64) * K + k0 + ss * 8);
        cpa16(dB + rr * SPAD + ss * 8,          Bp + (long)rr * K + k0 + ss * 8);
        cpa16(dB + (rr + 64) * SPAD + ss * 8,   Bp + (long)(rr + 64) * K + k0 + ss * 8);
    };

    auto compute = [&](int stg) {
        const __half* bA = sm + stg * 2 * (128 * SPAD);
        const __half* bB = bA + 128 * SPAD;
        #pragma unroll
        for (int ks = 0; ks < 2; ks++) {
            const int kb = ks * 16 + lkof;
            uint32_t bf[4][2];
            #pragma unroll
            for (int p = 0; p < 2; p++) {
                int n = wn * 32 + p * 16 + lrow;
                uint32_t r0, r1, r2, r3;
                ldmx4(r0, r1, r2, r3, smem_u32(bB + n * SPAD + kb));
                bf[2*p][0] = r0; bf[2*p+1][0] = r1; bf[2*p][1] = r2; bf[2*p+1][1] = r3;
            }
            #pragma unroll
            for (int mi = 0; mi < 4; mi++) {
                int mrow = wm * 64 + mi * 16 + lrow;
                uint32_t a[4];
                ldmx4(a[0], a[1], a[2], a[3], smem_u32(bA + mrow * SPAD + kb));
                #pragma unroll
                for (int ni = 0; ni < 4; ni++)
                    mma16h(acc[mi][ni], a, bf[ni]);
            }
        }
    };

    const int KT = K >> 5;
    load_stage(0, 0); cp_commit();
    for (int kt = 0; kt < KT; kt++) {
        if (kt + 1 < KT) { load_stage((kt + 1) & 1, (kt + 1) * 32); cp_commit(); cp_wait<1>(); }
        else             { cp_wait<0>(); }
        __syncthreads();
        compute(kt & 1);
        __syncthreads();
    }

    float*  Cz  = (EPI != 1) ? C  + z * zsC : nullptr;
    __half* Cfz = (EPI == 1) ? Cf + z * zsC : nullptr;

    #pragma unroll
    for (int mi = 0; mi < 4; mi++) {
        #pragma unroll
        for (int ni = 0; ni < 4; ni++) {
            int r0 = rowC + wm * 64 + mi * 16 + g;
            int cc = colC + wn * 32 + ni * 8 + 2 * t;
            float b0 = bz ? bz[cc] : 0.f, b1 = bz ? bz[cc + 1] : 0.f;
            float c00 = fmaf(acc[mi][ni][0], alpha, b0);
            float c01 = fmaf(acc[mi][ni][1], alpha, b1);
            float c10 = fmaf(acc[mi][ni][2], alpha, b0);
            float c11 = fmaf(acc[mi][ni][3], alpha, b1);
            if (EPI != 1) {
                float2 o0 = {c00, c01}, o1 = {c10, c11};
                *(float2*)(Cz + (long)r0 * N + cc)       = o0;
                *(float2*)(Cz + (long)(r0 + 8) * N + cc) = o1;
            } else {
                *(__half2*)(Cfz + (long)r0 * N + cc)       = __floats2half2_rn(c00, c01);
                *(__half2*)(Cfz + (long)(r0 + 8) * N + cc) = __floats2half2_rn(c10, c11);
            }
        }
    }

    if constexpr (EPI == 2) {
        __shared__ float redm[4][128];
        __shared__ float reds[4][128];
        float myM[8], myS[8];
        #pragma unroll
        for (int mi = 0; mi < 4; mi++) {
            #pragma unroll
            for (int h = 0; h < 2; h++) {
                float vv[8];
                #pragma unroll
                for (int ni = 0; ni < 4; ni++) {
                    vv[2*ni]   = acc[mi][ni][2*h]   * alpha;
                    vv[2*ni+1] = acc[mi][ni][2*h+1] * alpha;
                }
                float tm = vv[0];
                #pragma unroll
                for (int c = 1; c < 8; c++) tm = fmaxf(tm, vv[c]);
                float ts = 0.f;
                #pragma unroll
                for (int c = 0; c < 8; c++) ts += __expf(vv[c] - tm);
                #pragma unroll
                for (int off = 1; off <= 2; off <<= 1) {
                    float om = __shfl_xor_sync(0xffffffffu, tm, off);
                    float os = __shfl_xor_sync(0xffffffffu, ts, off);
                    float M = fmaxf(tm, om);
                    ts = ts * __expf(tm - M) + os * __expf(om - M);
                    tm = M;
                }
                myM[mi*2+h] = tm; myS[mi*2+h] = ts;
            }
        }
        if (t == 0) {
            #pragma unroll
            for (int mi = 0; mi < 4; mi++)
                #pragma unroll
                for (int h = 0; h < 2; h++) {
                    int row = wm * 64 + mi * 16 + g + h * 8;
                    redm[wn][row] = myM[mi*2+h];
                    reds[wn][row] = myS[mi*2+h];
                }
        }
        __syncthreads();
        if (wn == 0 && t == 0) {
            #pragma unroll
            for (int mi = 0; mi < 4; mi++)
                #pragma unroll
                for (int h = 0; h < 2; h++) {
                    int row = wm * 64 + mi * 16 + g + h * 8;
                    float M = redm[0][row];
                    #pragma unroll
                    for (int w = 1; w < 4; w++) M = fmaxf(M, redm[w][row]);
                    float S = 0.f;
                    #pragma unroll
                    for (int w = 0; w < 4; w++)
                        S += reds[w][row] * __expf(redm[w][row] - M);
                    long idx = (((long)z * 2048) + (rowC + row)) * 16 + blockIdx.x;
                    smOut[idx] = M;
                    ssOut[idx] = S;
                }
        }
    }
}

// ---------------------------------------------------------------------------
// gemm_pv: fused softmax-normalize + (P @ V) per (b,h).
//   Reads raw scores s from attn, folds 16 tile-stats/row, p=exp(s-m)*inv,
//   writes normalized p back to attn (the output), fp16 p -> smem,
//   1-pass fp16 MMA against pre-transposed fp16 V^T. Emits fp16 O.
// Block 128x64, BK=32, 256 thr. dyn smem = (2*128 + 2*64)*SPAD halves = 30720 B.
// ---------------------------------------------------------------------------
__global__ __launch_bounds__(256) void gemm_pv(
    float* __restrict__ attn,
    const __half* __restrict__ Vt, __half* __restrict__ O,
    const float* __restrict__ gsm, const float* __restrict__ gss)
{
    extern __shared__ __align__(16) __half smb[];
    __half* sP = smb;                       // [2][128*SPAD]
    __half* sV = smb + 2 * 128 * SPAD;      // [2][64*SPAD]
    __shared__ float sfm[128], sfi[128];

    const long z = blockIdx.z;
    const int  rb = blockIdx.y;
    float* Pp = attn + z * ATTN_STRIDE + (long)rb * 128 * 2048;
    const __half* Vp = Vt + z * HEAD_STRIDE;
    __half* Oz = O + z * HEAD_STRIDE + (long)rb * 128 * 64;

    const int tid = threadIdx.x, warp = tid >> 5, lane = tid & 31;
    const int g = lane >> 2, t = lane & 3, wm = warp >> 2, wn = warp & 3;
    const int lrow = lane & 15, lkof = (lane & 16) >> 1;

    // stats prologue: combine 16 tile stats per row
    if (tid < 128) {
        int rowg = rb * 128 + tid;
        const float* pm = gsm + ((((long)z * 2048) + rowg) << 4);
        const float* ps = gss + ((((long)z * 2048) + rowg) << 4);
        float M = pm[0];
        #pragma unroll
        for (int ct = 1; ct < 16; ct++) M = fmaxf(M, pm[ct]);
        float S = 0.f;
        #pragma unroll
        for (int ct = 0; ct < 16; ct++) S += ps[ct] * __expf(pm[ct] - M);
        sfm[tid] = M;
        sfi[tid] = 1.f / S;
    }
    __syncthreads();

    float acc[4][2][4];
    #pragma unroll
    for (int mi = 0; mi < 4; mi++)
        #pragma unroll
        for (int ni = 0; ni < 2; ni++)
            #pragma unroll
            for (int r = 0; r < 4; r++) acc[mi][ni][r] = 0.f;

    const int pr = tid >> 3, ps8 = tid & 7;       // P: rows pr+32i, 16B segs
    const int nr = tid >> 2, ns = tid & 3;        // V: row nr, seg ns

    float fmr[4], fir[4];
    #pragma unroll
    for (int i = 0; i < 4; i++) { fmr[i] = sfm[pr + i * 32]; fir[i] = sfi[pr + i * 32]; }

    float4 pregs[4];
    auto ldP = [&](int k0) {
        #pragma unroll
        for (int i = 0; i < 4; i++) {
            int lr = pr + i * 32;
            pregs[i] = *(const float4*)(Pp + (long)lr * 2048 + k0 + ps8 * 4);
        }
    };
    auto stsP = [&](int stg, int k0) {
        __half* d = sP + stg * 128 * SPAD;
        #pragma unroll
        for (int i = 0; i < 4; i++) {
            int lr = pr + i * 32;
            float vals[4] = {pregs[i].x, pregs[i].y, pregs[i].z, pregs[i].w};
            float pv[4];
            #pragma unroll
            for (int c = 0; c < 4; c++)
                pv[c] = __expf(vals[c] - fmr[i]) * fir[i];
            float4 o = {pv[0], pv[1], pv[2], pv[3]};
            *(float4*)(Pp + (long)lr * 2048 + k0 + ps8 * 4) = o;   // normalized attn out
            *(__half2*)(d + lr * SPAD + ps8 * 4)     = __floats2half2_rn(pv[0], pv[1]);
            *(__half2*)(d + lr * SPAD + ps8 * 4 + 2) = __floats2half2_rn(pv[2], pv[3]);
        }
    };
    auto loadV = [&](int stg, int k0) {
        cpa16(sV + stg * 64 * SPAD + nr * SPAD + ns * 8, Vp + (long)nr * 2048 + k0 + ns * 8);
    };

    auto compute = [&](int stg) {
        const __half* bP = sP + stg * 128 * SPAD;
        const __half* bV = sV + stg * 64 * SPAD;
        #pragma unroll
        for (int ks = 0; ks < 2; ks++) {
            const int kb = ks * 16 + lkof;
            uint32_t bv[2][2];
            {
                int n = wn * 16 + lrow;
                uint32_t r0, r1, r2, r3;
                ldmx4(r0, r1, r2, r3, smem_u32(bV + n * SPAD + kb));
                bv[0][0] = r0; bv[1][0] = r1; bv[0][1] = r2; bv[1][1] = r3;
            }
            #pragma unroll
            for (int mi = 0; mi < 4; mi++) {
                int m = wm * 64 + mi * 16 + lrow;
                uint32_t p[4];
                ldmx4(p[0], p[1], p[2], p[3], smem_u32(bP + m * SPAD + kb));
                mma16h(acc[mi][0], p, bv[0]);
                mma16h(acc[mi][1], p, bv[1]);
            }
        }
    };

    ldP(0);
    loadV(0, 0); cp_commit();
    for (int kt = 0; kt < 64; kt++) {
        stsP(kt & 1, kt * 32);
        cp_wait<0>();
        __syncthreads();
        if (kt + 1 < 64) {
            ldP((kt + 1) * 32);
            loadV((kt + 1) & 1, (kt + 1) * 32); cp_commit();
        }
        compute(kt & 1);
        __syncthreads();
    }

    #pragma unroll
    for (int mi = 0; mi < 4; mi++) {
        #pragma unroll
        for (int ni = 0; ni < 2; ni++) {
            int r0 = wm * 64 + mi * 16 + g;
            int cc = wn * 16 + ni * 8 + 2 * t;
            *(__half2*)(Oz + (long)r0 * 64 + cc)       = __floats2half2_rn(acc[mi][ni][0], acc[mi][ni][1]);
            *(__half2*)(Oz + (long)(r0 + 8) * 64 + cc) = __floats2half2_rn(acc[mi][ni][2], acc[mi][ni][3]);
        }
    }
}

// ---------------------------------------------------------------------------
extern "C" void kernel_launch(void* const* d_in, const int* in_sizes, int n_in,
                              void* d_out, int out_size)
{
    const float* pre_q = (const float*)d_in[0];
    const float* pre_k = (const float*)d_in[1];
    const float* pre_v = (const float*)d_in[2];
    const float* Wq = (const float*)d_in[3];
    const float* bq = (const float*)d_in[4];
    const float* Wk = (const float*)d_in[5];
    const float* bk = (const float*)d_in[6];
    const float* Wv = (const float*)d_in[7];
    const float* bv = (const float*)d_in[8];
    const float* Wo = (const float*)d_in[9];
    const float* bo = (const float*)d_in[10];

    float* proj = (float*)d_out;
    float* attn = proj + PROJ_ELEMS;

    __half *pre16, *W16, *Wo16, *QKV16, *Vt16, *O16;
    float *bias3, *smp, *ssp;
    cudaGetSymbolAddress((void**)&pre16, g_pre16);
    cudaGetSymbolAddress((void**)&W16, g_W16);
    cudaGetSymbolAddress((void**)&Wo16, g_Wo16);
    cudaGetSymbolAddress((void**)&bias3, g_bias3);
    cudaGetSymbolAddress((void**)&QKV16, g_QKV16);
    cudaGetSymbolAddress((void**)&Vt16, g_Vt16);
    cudaGetSymbolAddress((void**)&O16, g_O16);
    cudaGetSymbolAddress((void**)&smp, g_sm);
    cudaGetSymbolAddress((void**)&ssp, g_ss);

    static bool attr_done = false;
    if (!attr_done) {
        cudaFuncSetAttribute(gemm1<0>, cudaFuncAttributeMaxDynamicSharedMemorySize, 40960);
        cudaFuncSetAttribute(gemm1<1>, cudaFuncAttributeMaxDynamicSharedMemorySize, 40960);
        cudaFuncSetAttribute(gemm1<2>, cudaFuncAttributeMaxDynamicSharedMemorySize, 40960);
        cudaFuncSetAttribute(gemm_pv,  cudaFuncAttributeMaxDynamicSharedMemorySize, 30720);
        attr_done = true;
    }

    // launch 0: biases
    biascopy<<<4, 256>>>(bq, bk, bv, bias3);

    // launch 1: all 7 fp32->fp16 conversions
    CJobs js;
    js.j[0] = { (const float4*)pre_q, pre16,           1048576 };
    js.j[1] = { (const float4*)pre_k, pre16 + 4194304, 1048576 };
    js.j[2] = { (const float4*)pre_v, pre16 + 8388608, 1048576 };
    js.j[3] = { (const float4*)Wq,    W16,             262144 };
    js.j[4] = { (const float4*)Wk,    W16 + 1048576,   262144 };
    js.j[5] = { (const float4*)Wv,    W16 + 2097152,   262144 };
    js.j[6] = { (const float4*)Wo,    Wo16,            262144 };
    cvt_all<<<dim3(4096, 7), 256>>>(js);

    // launch 2: QKV projections (merged z=3), fp16 outputs
    gemm1<1><<<dim3(8, 32, 3), 256, 40960>>>(
        pre16, W16, bias3, nullptr, QKV16,
        4096, 1024, 1024, 1.f, 4194304, 1048576, 4194304, 1024, nullptr, nullptr);

    // launch 3: transpose V per head
    transposeV<<<dim3(32, 32), 256>>>(QKV16 + 8388608, Vt16);

    // launch 4: scores + per-tile stats -> attn raw (fp32)
    gemm1<2><<<dim3(16, 16, 32), 256, 40960>>>(
        QKV16, QKV16 + 4194304, nullptr, attn, nullptr,
        2048, 2048, 64, 0.125f, HEAD_STRIDE, HEAD_STRIDE, ATTN_STRIDE, 0, smp, ssp);

    // launch 5: fused softmax-normalize + P@V (writes normalized attn, fp16 O)
    gemm_pv<<<dim3(1, 16, 32), 256, 30720>>>(attn, Vt16, O16, smp, ssp);

    // launch 6: output projection
    gemm1<0><<<dim3(8, 32, 1), 256, 40960>>>(
        O16, Wo16, bo, proj, nullptr,
        4096, 1024, 1024, 1.f, 0, 0, 0, 0, nullptr, nullptr);
}

// round 14
// speedup vs baseline: 1.8346x; 1.0981x over previous
#include <cuda_runtime.h>
#include <cuda_fp16.h>
#include <cstdint>

// Shapes (fixed): B=2, S=2048, D=1024, H=16, d=64
// head h of batch b = contiguous block (b*2048 + h*128)*1024 viewed as [2048,64] row-major
// d_out = [ proj : 4194304 f32 ][ attn : 134217728 f32 ]

#define PROJ_ELEMS 4194304LL
#define HEAD_STRIDE 131072LL
#define ATTN_STRIDE 4194304LL

// ---------------- persistent device-global scratch ----------------
__device__ __half g_pre16[12582912];   // pre_q|pre_k|pre_v
__device__ __half g_W16[3145728];      // Wq|Wk|Wv
__device__ __half g_Wo16[1048576];
__device__ float  g_bias3[3072];       // bq|bk|bv
__device__ __half g_QKV16[12582912];   // Q|K|V
__device__ __half g_Vt16[4194304];     // V transposed [head][64][2048]
__device__ __half g_O16[4194304];
__device__ __half g_E16[134217728];    // e = exp(s - tileMax), fp16, [head][row][2048]
__device__ float  g_sm[1048576];       // per (head,row,colTile) tile row-max [32][2048][16]
__device__ float  g_ss[1048576];       // per (head,row,colTile) tile expsum

// ---------------- helpers ----------------
__device__ __forceinline__ uint32_t smem_u32(const void* p) {
    return (uint32_t)__cvta_generic_to_shared(p);
}
__device__ __forceinline__ void cpa16(void* s, const void* g) {
    asm volatile("cp.async.cg.shared.global [%0], [%1], 16;"
                 :: "r"(smem_u32(s)), "l"(__cvta_generic_to_global(g)));
}
__device__ __forceinline__ void cp_commit() { asm volatile("cp.async.commit_group;"); }
template<int NW> __device__ __forceinline__ void cp_wait() {
    asm volatile("cp.async.wait_group %0;" :: "n"(NW));
}
__device__ __forceinline__ void ldmx4(uint32_t& r0, uint32_t& r1, uint32_t& r2, uint32_t& r3,
                                      uint32_t addr) {
    asm volatile("ldmatrix.sync.aligned.m8n8.x4.shared.b16 {%0,%1,%2,%3}, [%4];"
                 : "=r"(r0), "=r"(r1), "=r"(r2), "=r"(r3) : "r"(addr));
}
__device__ __forceinline__ void mma16h(float* c, const uint32_t* a, const uint32_t* b) {
    asm volatile(
        "mma.sync.aligned.m16n8k16.row.col.f32.f16.f16.f32 "
        "{%0,%1,%2,%3},{%4,%5,%6,%7},{%8,%9},{%0,%1,%2,%3};"
        : "+f"(c[0]), "+f"(c[1]), "+f"(c[2]), "+f"(c[3])
        : "r"(a[0]), "r"(a[1]), "r"(a[2]), "r"(a[3]), "r"(b[0]), "r"(b[1]));
}

#define SPAD 40   // smem row stride (halves): 32 data + 8 pad -> conflict-free ldmatrix

// ---------------------------------------------------------------------------
// prep: all 7 fp32->fp16 conversions in ONE launch
// ---------------------------------------------------------------------------
struct CJob { const float4* s; __half* h; int n4; };
struct CJobs { CJob j[7]; };

__global__ void cvt_all(CJobs js)
{
    CJob jb = js.j[blockIdx.y];
    int i = blockIdx.x * blockDim.x + threadIdx.x;
    if (i >= jb.n4) return;
    float4 v = jb.s[i];
    __half2 a = __floats2half2_rn(v.x, v.y);
    __half2 b = __floats2half2_rn(v.z, v.w);
    *(__half2*)(jb.h + 4 * i)     = a;
    *(__half2*)(jb.h + 4 * i + 2) = b;
}

__global__ void biascopy(const float* __restrict__ bq, const float* __restrict__ bk,
                         const float* __restrict__ bv, float* __restrict__ dst)
{
    int i = blockIdx.x * blockDim.x + threadIdx.x;
    if (i < 1024) { dst[i] = bq[i]; dst[1024 + i] = bk[i]; dst[2048 + i] = bv[i]; }
}

// Transpose V per head: [2048,64] -> [64,2048].
__global__ __launch_bounds__(256) void transposeV(
    const __half* __restrict__ V, __half* __restrict__ Vt)
{
    __shared__ __half th[64][72];
    const long head = blockIdx.y;
    const int  k0   = blockIdx.x * 64;
    const __half* in = V + head * HEAD_STRIDE + (long)k0 * 64;
    __half* out = Vt + head * HEAD_STRIDE + k0;

    const int tid = threadIdx.x;
    const int lr = tid >> 2, seg = tid & 3;
    #pragma unroll
    for (int i = 0; i < 2; i++) {
        int col = seg * 16 + i * 8;
        *(uint4*)&th[lr][col] = *(const uint4*)(in + (long)lr * 64 + col);
    }
    __syncthreads();
    #pragma unroll
    for (int i = 0; i < 2; i++) {
        int kk = seg * 16 + i * 8;
        __half e[8];
        #pragma unroll
        for (int j = 0; j < 8; j++) e[j] = th[kk + j][lr];
        *(uint4*)(out + (long)lr * 2048 + kk) = *(uint4*)e;
    }
}

// ---------------------------------------------------------------------------
// gemm1: 1-pass fp16 NT GEMM (fp32 accumulate), cp.async 2-stage pipelined.
//   EPI=0: fp32 C (+bias).  EPI=1: fp16 Cf (+bias).
//   EPI=2: scores mode — NO C write; e=exp(alpha*s - tileMax) fp16 -> Cf,
//          per-tile row stats (max, expsum) -> smOut/ssOut.
// Block 128x128, BK=32, 256 threads (8 warps 2x4), warp tile 64x32.
// dyn smem = 40960 B.
// ---------------------------------------------------------------------------
template<int EPI>
__global__ __launch_bounds__(256) void gemm1(
    const __half* __restrict__ A, const __half* __restrict__ B,
    const float* __restrict__ bias, float* __restrict__ C, __half* __restrict__ Cf,
    int M, int N, int K, float alpha,
    long zsA, long zsB, long zsC, int zsBias,
    float* __restrict__ smOut, float* __restrict__ ssOut)
{
    extern __shared__ __align__(16) __half sm[];
    const long z = blockIdx.z;
    A += z * zsA; B += z * zsB;
    const float* bz = bias ? bias + (long)z * zsBias : nullptr;

    const int tid = threadIdx.x, warp = tid >> 5, lane = tid & 31;
    const int g = lane >> 2, t = lane & 3, wm = warp >> 2, wn = warp & 3;
    const int lrow = lane & 15, lkof = (lane & 16) >> 1;
    const int rowC = blockIdx.y * 128, colC = blockIdx.x * 128;

    const __half* Ap = A + (long)rowC * K;
    const __half* Bp = B + (long)colC * K;

    float acc[4][4][4];
    #pragma unroll
    for (int mi = 0; mi < 4; mi++)
        #pragma unroll
        for (int ni = 0; ni < 4; ni++)
            #pragma unroll
            for (int r = 0; r < 4; r++) acc[mi][ni][r] = 0.f;

    const int rr = tid >> 2, ss = tid & 3;

    auto load_stage = [&](int stg, int k0) {
        __half* dA = sm + stg * 2 * (128 * SPAD);
        __half* dB = dA + 128 * SPAD;
        cpa16(dA + rr * SPAD + ss * 8,          Ap + (long)rr * K + k0 + ss * 8);
        cpa16(dA + (rr + 64) * SPAD + ss * 8,   Ap + (long)(rr + 64) * K + k0 + ss * 8);
        cpa16(dB + rr * SPAD + ss * 8,          Bp + (long)rr * K + k0 + ss * 8);
        cpa16(dB + (rr + 64) * SPAD + ss * 8,   Bp + (long)(rr + 64) * K + k0 + ss * 8);
    };

    auto compute = [&](int stg) {
        const __half* bA = sm + stg * 2 * (128 * SPAD);
        const __half* bB = bA + 128 * SPAD;
        #pragma unroll
        for (int ks = 0; ks < 2; ks++) {
            const int kb = ks * 16 + lkof;
            uint32_t bf[4][2];
            #pragma unroll
            for (int p = 0; p < 2; p++) {
                int n = wn * 32 + p * 16 + lrow;
                uint32_t r0, r1, r2, r3;
                ldmx4(r0, r1, r2, r3, smem_u32(bB + n * SPAD + kb));
                bf[2*p][0] = r0; bf[2*p+1][0] = r1; bf[2*p][1] = r2; bf[2*p+1][1] = r3;
            }
            #pragma unroll
            for (int mi = 0; mi < 4; mi++) {
                int mrow = wm * 64 + mi * 16 + lrow;
                uint32_t a[4];
                ldmx4(a[0], a[1], a[2], a[3], smem_u32(bA + mrow * SPAD + kb));
                #pragma unroll
                for (int ni = 0; ni < 4; ni++)
                    mma16h(acc[mi][ni], a, bf[ni]);
            }
        }
    };

    const int KT = K >> 5;
    load_stage(0, 0); cp_commit();
    for (int kt = 0; kt < KT; kt++) {
        if (kt + 1 < KT) { load_stage((kt + 1) & 1, (kt + 1) * 32); cp_commit(); cp_wait<1>(); }
        else             { cp_wait<0>(); }
        __syncthreads();
        compute(kt & 1);
        __syncthreads();
    }

    if constexpr (EPI == 0 || EPI == 1) {
        float*  Cz  = (EPI == 0) ? C  + z * zsC : nullptr;
        __half* Cfz = (EPI == 1) ? Cf + z * zsC : nullptr;
        #pragma unroll
        for (int mi = 0; mi < 4; mi++) {
            #pragma unroll
            for (int ni = 0; ni < 4; ni++) {
                int r0 = rowC + wm * 64 + mi * 16 + g;
                int cc = colC + wn * 32 + ni * 8 + 2 * t;
                float b0 = bz ? bz[cc] : 0.f, b1 = bz ? bz[cc + 1] : 0.f;
                float c00 = fmaf(acc[mi][ni][0], alpha, b0);
                float c01 = fmaf(acc[mi][ni][1], alpha, b1);
                float c10 = fmaf(acc[mi][ni][2], alpha, b0);
                float c11 = fmaf(acc[mi][ni][3], alpha, b1);
                if (EPI == 0) {
                    float2 o0 = {c00, c01}, o1 = {c10, c11};
                    *(float2*)(Cz + (long)r0 * N + cc)       = o0;
                    *(float2*)(Cz + (long)(r0 + 8) * N + cc) = o1;
                } else {
                    *(__half2*)(Cfz + (long)r0 * N + cc)       = __floats2half2_rn(c00, c01);
                    *(__half2*)(Cfz + (long)(r0 + 8) * N + cc) = __floats2half2_rn(c10, c11);
                }
            }
        }
    }

    if constexpr (EPI == 2) {
        __shared__ float redm[4][128];
        __shared__ float reds[4][128];
        __shared__ float fM[128];
        // ---- pass A: tile row max ----
        #pragma unroll
        for (int mi = 0; mi < 4; mi++) {
            #pragma unroll
            for (int h = 0; h < 2; h++) {
                float tm = -1e30f;
                #pragma unroll
                for (int ni = 0; ni < 4; ni++) {
                    tm = fmaxf(tm, acc[mi][ni][2*h]);
                    tm = fmaxf(tm, acc[mi][ni][2*h+1]);
                }
                tm *= alpha;   // alpha > 0: max commutes
                #pragma unroll
                for (int off = 1; off <= 2; off <<= 1)
                    tm = fmaxf(tm, __shfl_xor_sync(0xffffffffu, tm, off));
                if (t == 0) redm[wn][wm * 64 + mi * 16 + g + h * 8] = tm;
            }
        }
        __syncthreads();
        if (tid < 128)
            fM[tid] = fmaxf(fmaxf(redm[0][tid], redm[1][tid]),
                            fmaxf(redm[2][tid], redm[3][tid]));
        __syncthreads();
        // ---- pass B: e = exp(s - M), store fp16, expsum ----
        __half* Ez = Cf + z * zsC;
        #pragma unroll
        for (int mi = 0; mi < 4; mi++) {
            #pragma unroll
            for (int h = 0; h < 2; h++) {
                int row = wm * 64 + mi * 16 + g + h * 8;
                float Mv = fM[row];
                float ts = 0.f;
                #pragma unroll
                for (int ni = 0; ni < 4; ni++) {
                    float e0 = __expf(fmaf(acc[mi][ni][2*h],   alpha, -Mv));
                    float e1 = __expf(fmaf(acc[mi][ni][2*h+1], alpha, -Mv));
                    ts += e0 + e1;
                    int cc = colC + wn * 32 + ni * 8 + 2 * t;
                    *(__half2*)(Ez + (long)(rowC + row) * N + cc) = __floats2half2_rn(e0, e1);
                }
                #pragma unroll
                for (int off = 1; off <= 2; off <<= 1)
                    ts += __shfl_xor_sync(0xffffffffu, ts, off);
                if (t == 0) reds[wn][row] = ts;
            }
        }
        __syncthreads();
        if (tid < 128) {
            float S = reds[0][tid] + reds[1][tid] + reds[2][tid] + reds[3][tid];
            long idx = (((long)z * 2048) + (rowC + tid)) * 16 + blockIdx.x;
            smOut[idx] = fM[tid];
            ssOut[idx] = S;
        }
    }
}

// ---------------------------------------------------------------------------
// gemm_pv: exp-free fused normalize + (P @ V) per (b,h).
//   Reads e (fp16) from E, prologue builds per-(row,tile) factor
//   f = exp(m_t - M)/S; fill path: p = e*f, writes fp32 p to attn (output),
//   fp16 p -> smem, 1-pass fp16 MMA vs pre-transposed V^T. Emits fp16 O.
// Block 128x64, BK=32, 256 thr. dyn smem = (2*128 + 2*64)*SPAD halves = 30720 B.
// ---------------------------------------------------------------------------
__global__ __launch_bounds__(256) void gemm_pv(
    const __half* __restrict__ E, float* __restrict__ attn,
    const __half* __restrict__ Vt, __half* __restrict__ O,
    const float* __restrict__ gsm, const float* __restrict__ gss)
{
    extern __shared__ __align__(16) __half smb[];
    __half* sP = smb;                       // [2][128*SPAD]
    __half* sV = smb + 2 * 128 * SPAD;      // [2][64*SPAD]
    __shared__ float sfac[128][17];

    const long z = blockIdx.z;
    const int  rb = blockIdx.y;
    const __half* Ep = E + z * ATTN_STRIDE + (long)rb * 128 * 2048;
    float* Pp = attn + z * ATTN_STRIDE + (long)rb * 128 * 2048;
    const __half* Vp = Vt + z * HEAD_STRIDE;
    __half* Oz = O + z * HEAD_STRIDE + (long)rb * 128 * 64;

    const int tid = threadIdx.x, warp = tid >> 5, lane = tid & 31;
    const int g = lane >> 2, t = lane & 3, wm = warp >> 2, wn = warp & 3;
    const int lrow = lane & 15, lkof = (lane & 16) >> 1;

    // ---- prologue: per-(row,tile) scale factors ----
    if (tid < 128) {
        int rowg = rb * 128 + tid;
        const float* pm = gsm + ((((long)z * 2048) + rowg) << 4);
        const float* ps = gss + ((((long)z * 2048) + rowg) << 4);
        float M = pm[0];
        #pragma unroll
        for (int ct = 1; ct < 16; ct++) M = fmaxf(M, pm[ct]);
        float w[16];
        float S = 0.f;
        #pragma unroll
        for (int ct = 0; ct < 16; ct++) {
            w[ct] = __expf(pm[ct] - M);
            S += ps[ct] * w[ct];
        }
        float inv = 1.f / S;
        #pragma unroll
        for (int ct = 0; ct < 16; ct++) sfac[tid][ct] = w[ct] * inv;
    }
    __syncthreads();

    float acc[4][2][4];
    #pragma unroll
    for (int mi = 0; mi < 4; mi++)
        #pragma unroll
        for (int ni = 0; ni < 2; ni++)
            #pragma unroll
            for (int r = 0; r < 4; r++) acc[mi][ni][r] = 0.f;

    const int nr = tid >> 2, ns = tid & 3;   // V loader

    uint4 eregs[2];
    auto ldE = [&](int k0) {
        #pragma unroll
        for (int i = 0; i < 2; i++) {
            int idx = tid + i * 256, row = idx >> 2, seg = idx & 3;
            eregs[i] = *(const uint4*)(Ep + (long)row * 2048 + k0 + seg * 8);
        }
    };
    auto stsP = [&](int stg, int k0) {
        __half* d = sP + stg * 128 * SPAD;
        const int tile = k0 >> 7;
        #pragma unroll
        for (int i = 0; i < 2; i++) {
            int idx = tid + i * 256, row = idx >> 2, seg = idx & 3;
            float f = sfac[row][tile];
            __half eh[8];
            *(uint4*)eh = eregs[i];
            float p[8];
            #pragma unroll
            for (int c = 0; c < 8; c++) p[c] = __half2float(eh[c]) * f;
            float4 o0 = {p[0], p[1], p[2], p[3]};
            float4 o1 = {p[4], p[5], p[6], p[7]};
            *(float4*)(Pp + (long)row * 2048 + k0 + seg * 8)     = o0;
            *(float4*)(Pp + (long)row * 2048 + k0 + seg * 8 + 4) = o1;
            __half2* ds = (__half2*)(d + row * SPAD + seg * 8);
            ds[0] = __floats2half2_rn(p[0], p[1]);
            ds[1] = __floats2half2_rn(p[2], p[3]);
            ds[2] = __floats2half2_rn(p[4], p[5]);
            ds[3] = __floats2half2_rn(p[6], p[7]);
        }
    };
    auto loadV = [&](int stg, int k0) {
        cpa16(sV + stg * 64 * SPAD + nr * SPAD + ns * 8, Vp + (long)nr * 2048 + k0 + ns * 8);
    };

    auto compute = [&](int stg) {
        const __half* bP = sP + stg * 128 * SPAD;
        const __half* bV = sV + stg * 64 * SPAD;
        #pragma unroll
        for (int ks = 0; ks < 2; ks++) {
            const int kb = ks * 16 + lkof;
            uint32_t bv[2][2];
            {
                int n = wn * 16 + lrow;
                uint32_t r0, r1, r2, r3;
                ldmx4(r0, r1, r2, r3, smem_u32(bV + n * SPAD + kb));
                bv[0][0] = r0; bv[1][0] = r1; bv[0][1] = r2; bv[1][1] = r3;
            }
            #pragma unroll
            for (int mi = 0; mi < 4; mi++) {
                int m = wm * 64 + mi * 16 + lrow;
                uint32_t p[4];
                ldmx4(p[0], p[1], p[2], p[3], smem_u32(bP + m * SPAD + kb));
                mma16h(acc[mi][0], p, bv[0]);
                mma16h(acc[mi][1], p, bv[1]);
            }
        }
    };

    ldE(0);
    loadV(0, 0); cp_commit();
    for (int kt = 0; kt < 64; kt++) {
        stsP(kt & 1, kt * 32);
        cp_wait<0>();
        __syncthreads();
        if (kt + 1 < 64) {
            ldE((kt + 1) * 32);
            loadV((kt + 1) & 1, (kt + 1) * 32); cp_commit();
        }
        compute(kt & 1);
        __syncthreads();
    }

    #pragma unroll
    for (int mi = 0; mi < 4; mi++) {
        #pragma unroll
        for (int ni = 0; ni < 2; ni++) {
            int r0 = wm * 64 + mi * 16 + g;
            int cc = wn * 16 + ni * 8 + 2 * t;
            *(__half2*)(Oz + (long)r0 * 64 + cc)       = __floats2half2_rn(acc[mi][ni][0], acc[mi][ni][1]);
            *(__half2*)(Oz + (long)(r0 + 8) * 64 + cc) = __floats2half2_rn(acc[mi][ni][2], acc[mi][ni][3]);
        }
    }
}

// ---------------------------------------------------------------------------
extern "C" void kernel_launch(void* const* d_in, const int* in_sizes, int n_in,
                              void* d_out, int out_size)
{
    const float* pre_q = (const float*)d_in[0];
    const float* pre_k = (const float*)d_in[1];
    const float* pre_v = (const float*)d_in[2];
    const float* Wq = (const float*)d_in[3];
    const float* bq = (const float*)d_in[4];
    const float* Wk = (const float*)d_in[5];
    const float* bk = (const float*)d_in[6];
    const float* Wv = (const float*)d_in[7];
    const float* bv = (const float*)d_in[8];
    const float* Wo = (const float*)d_in[9];
    const float* bo = (const float*)d_in[10];

    float* proj = (float*)d_out;
    float* attn = proj + PROJ_ELEMS;

    __half *pre16, *W16, *Wo16, *QKV16, *Vt16, *O16, *E16;
    float *bias3, *smp, *ssp;
    cudaGetSymbolAddress((void**)&pre16, g_pre16);
    cudaGetSymbolAddress((void**)&W16, g_W16);
    cudaGetSymbolAddress((void**)&Wo16, g_Wo16);
    cudaGetSymbolAddress((void**)&bias3, g_bias3);
    cudaGetSymbolAddress((void**)&QKV16, g_QKV16);
    cudaGetSymbolAddress((void**)&Vt16, g_Vt16);
    cudaGetSymbolAddress((void**)&O16, g_O16);
    cudaGetSymbolAddress((void**)&E16, g_E16);
    cudaGetSymbolAddress((void**)&smp, g_sm);
    cudaGetSymbolAddress((void**)&ssp, g_ss);

    static bool attr_done = false;
    if (!attr_done) {
        cudaFuncSetAttribute(gemm1<0>, cudaFuncAttributeMaxDynamicSharedMemorySize, 40960);
        cudaFuncSetAttribute(gemm1<1>, cudaFuncAttributeMaxDynamicSharedMemorySize, 40960);
        cudaFuncSetAttribute(gemm1<2>, cudaFuncAttributeMaxDynamicSharedMemorySize, 40960);
        cudaFuncSetAttribute(gemm_pv,  cudaFuncAttributeMaxDynamicSharedMemorySize, 30720);
        attr_done = true;
    }

    // launch 0: biases
    biascopy<<<4, 256>>>(bq, bk, bv, bias3);

    // launch 1: all 7 fp32->fp16 conversions
    CJobs js;
    js.j[0] = { (const float4*)pre_q, pre16,           1048576 };
    js.j[1] = { (const float4*)pre_k, pre16 + 4194304, 1048576 };
    js.j[2] = { (const float4*)pre_v, pre16 + 8388608, 1048576 };
    js.j[3] = { (const float4*)Wq,    W16,             262144 };
    js.j[4] = { (const float4*)Wk,    W16 + 1048576,   262144 };
    js.j[5] = { (const float4*)Wv,    W16 + 2097152,   262144 };
    js.j[6] = { (const float4*)Wo,    Wo16,            262144 };
    cvt_all<<<dim3(4096, 7), 256>>>(js);

    // launch 2: QKV projections (merged z=3), fp16 outputs
    gemm1<1><<<dim3(8, 32, 3), 256, 40960>>>(
        pre16, W16, bias3, nullptr, QKV16,
        4096, 1024, 1024, 1.f, 4194304, 1048576, 4194304, 1024, nullptr, nullptr);

    // launch 3: transpose V per head
    transposeV<<<dim3(32, 32), 256>>>(QKV16 + 8388608, Vt16);

    // launch 4: scores -> e (fp16) + per-tile stats (no attn write)
    gemm1<2><<<dim3(16, 16, 32), 256, 40960>>>(
        QKV16, QKV16 + 4194304, nullptr, nullptr, E16,
        2048, 2048, 64, 0.125f, HEAD_STRIDE, HEAD_STRIDE, ATTN_STRIDE, 0, smp, ssp);

    // launch 5: exp-free normalize + P@V (writes normalized attn, fp16 O)
    gemm_pv<<<dim3(1, 16, 32), 256, 30720>>>(E16, attn, Vt16, O16, smp, ssp);

    // launch 6: output projection
    gemm1<0><<<dim3(8, 32, 1), 256, 40960>>>(
        O16, Wo16, bo, proj, nullptr,
        4096, 1024, 1024, 1.f, 0, 0, 0, 0, nullptr, nullptr);
}